// round 8
// baseline (speedup 1.0000x reference)
#include <cuda_runtime.h>
#include <cuda_bf16.h>
#include <cstdint>

#define NU 100000
#define NE 1600000
#define NB 16384
#define D  128
#define SCAN_B 98   // ceil(NU / 1024)

typedef unsigned long long u64;

// ---- static scratch (no allocations allowed) ----
static __device__ int   g_rowptr[NU + 1];
static __device__ int   g_cursor[NU];
static __device__ int   g_esrc[NE];
static __device__ int   g_bsum[SCAN_B];
static __device__ int   g_boff[SCAN_B];
static __device__ float g_h1 [(size_t)NU * D];   // layer-1 user output
static __device__ float g_hn [(size_t)NU * D];   // layer-1 neighbor mean
static __device__ float g_hn2[(size_t)NB * D];   // layer-2 neighbor mean
// prepped dense1 weights: [part][n][k] bf16, part: 0=Ws_hi 1=Ws_lo 2=Wn_hi 3=Wn_lo
static __device__ __nv_bfloat16 g_wq[4 * 128 * 128];

// ---------------- packed f32x2 helpers ----------------
__device__ __forceinline__ u64 dup2(float x) {
    u64 r; asm("mov.b64 %0, {%1, %1};" : "=l"(r) : "f"(x)); return r;
}
__device__ __forceinline__ void ffma2(u64& d, u64 a, u64 b) {
    asm("fma.rn.f32x2 %0, %1, %2, %0;" : "+l"(d) : "l"(a), "l"(b));
}
__device__ __forceinline__ float2 unpk(u64 v) {
    float2 r; asm("mov.b64 {%0, %1}, %2;" : "=f"(r.x), "=f"(r.y) : "l"(v)); return r;
}

// ---------------- mma.sync helpers (plain sm_80+ PTX, no 'a' features) ----------------
__device__ __forceinline__ uint32_t smem_u32(const void* p) {
    uint32_t a;
    asm("{ .reg .u64 t; cvta.to.shared.u64 t, %1; cvt.u32.u64 %0, t; }" : "=r"(a) : "l"(p));
    return a;
}
__device__ __forceinline__ void ldsm_x4(uint32_t* r, uint32_t addr) {
    asm volatile("ldmatrix.sync.aligned.m8n8.x4.shared.b16 {%0,%1,%2,%3}, [%4];"
        : "=r"(r[0]), "=r"(r[1]), "=r"(r[2]), "=r"(r[3]) : "r"(addr));
}
__device__ __forceinline__ void ldsm_x2(uint32_t* r, uint32_t addr) {
    asm volatile("ldmatrix.sync.aligned.m8n8.x2.shared.b16 {%0,%1}, [%2];"
        : "=r"(r[0]), "=r"(r[1]) : "r"(addr));
}
__device__ __forceinline__ void mma_bf16(float* c, const uint32_t* a, const uint32_t* b) {
    asm volatile("mma.sync.aligned.m16n8k16.row.col.f32.bf16.bf16.f32 "
        "{%0,%1,%2,%3}, {%4,%5,%6,%7}, {%8,%9}, {%0,%1,%2,%3};"
        : "+f"(c[0]), "+f"(c[1]), "+f"(c[2]), "+f"(c[3])
        : "r"(a[0]), "r"(a[1]), "r"(a[2]), "r"(a[3]), "r"(b[0]), "r"(b[1]));
}

// ---------------- CSR build ----------------
__global__ void k_zero() {
    int i = blockIdx.x * blockDim.x + threadIdx.x;
    if (i < NU) g_cursor[i] = 0;
}

__global__ void k_count(const int* __restrict__ dst) {
    int i = blockIdx.x * blockDim.x + threadIdx.x;
    if (i < NE / 8) {
        int4 d0 = ((const int4*)dst)[2 * i];
        int4 d1 = ((const int4*)dst)[2 * i + 1];
        atomicAdd(&g_cursor[d0.x], 1); atomicAdd(&g_cursor[d0.y], 1);
        atomicAdd(&g_cursor[d0.z], 1); atomicAdd(&g_cursor[d0.w], 1);
        atomicAdd(&g_cursor[d1.x], 1); atomicAdd(&g_cursor[d1.y], 1);
        atomicAdd(&g_cursor[d1.z], 1); atomicAdd(&g_cursor[d1.w], 1);
    }
}

__global__ __launch_bounds__(1024) void k_scan_local() {
    __shared__ int sh[1024];
    const int t = threadIdx.x;
    const int i = blockIdx.x * 1024 + t;
    int c = (i < NU) ? g_cursor[i] : 0;
    int val = c;
    sh[t] = val;
    __syncthreads();
#pragma unroll
    for (int off = 1; off < 1024; off <<= 1) {
        int tmp = (t >= off) ? sh[t - off] : 0;
        __syncthreads();
        val += tmp;
        sh[t] = val;
        __syncthreads();
    }
    if (i < NU) g_rowptr[i] = val - c;
    if (t == 1023) g_bsum[blockIdx.x] = val;
}

__global__ __launch_bounds__(128) void k_scan_top() {
    __shared__ int sh[128];
    const int t = threadIdx.x;
    int v = (t < SCAN_B) ? g_bsum[t] : 0;
    int val = v;
    sh[t] = val;
    __syncthreads();
#pragma unroll
    for (int off = 1; off < 128; off <<= 1) {
        int tmp = (t >= off) ? sh[t - off] : 0;
        __syncthreads();
        val += tmp;
        sh[t] = val;
        __syncthreads();
    }
    if (t < SCAN_B) g_boff[t] = val - v;
}

__global__ void k_scan_add() {
    int i = blockIdx.x * blockDim.x + threadIdx.x;
    if (i < NU) {
        int r = g_rowptr[i] + g_boff[i >> 10];
        g_rowptr[i] = r;
        g_cursor[i] = r;
    }
    if (i == 0) g_rowptr[NU] = NE;
}

__global__ void k_scatter(const int* __restrict__ src, const int* __restrict__ dst) {
    int i = blockIdx.x * blockDim.x + threadIdx.x;
    if (i < NE / 8) {
        int4 d0 = ((const int4*)dst)[2 * i];
        int4 d1 = ((const int4*)dst)[2 * i + 1];
        int4 s0 = ((const int4*)src)[2 * i];
        int4 s1 = ((const int4*)src)[2 * i + 1];
        int p0 = atomicAdd(&g_cursor[d0.x], 1);
        int p1 = atomicAdd(&g_cursor[d0.y], 1);
        int p2 = atomicAdd(&g_cursor[d0.z], 1);
        int p3 = atomicAdd(&g_cursor[d0.w], 1);
        int p4 = atomicAdd(&g_cursor[d1.x], 1);
        int p5 = atomicAdd(&g_cursor[d1.y], 1);
        int p6 = atomicAdd(&g_cursor[d1.z], 1);
        int p7 = atomicAdd(&g_cursor[d1.w], 1);
        g_esrc[p0] = s0.x; g_esrc[p1] = s0.y; g_esrc[p2] = s0.z; g_esrc[p3] = s0.w;
        g_esrc[p4] = s1.x; g_esrc[p5] = s1.y; g_esrc[p6] = s1.z; g_esrc[p7] = s1.w;
    }
}

// ---------------- high-occupancy neighbor-mean aggregation ----------------
__device__ __forceinline__ void agg_row(
    const float* __restrict__ table, int row, int lane, float* __restrict__ dstv)
{
    int beg = g_rowptr[row], end = g_rowptr[row + 1];
    int deg = end - beg;
    float4 a = make_float4(0.f, 0.f, 0.f, 0.f);
    for (int base = 0; base < deg; base += 32) {
        int rem = deg - base;
        int n = rem < 32 ? rem : 32;
        int myi = (lane < n) ? g_esrc[beg + base + lane] : 0;
        int j = 0;
        for (; j + 8 <= n; j += 8) {
            int s0 = __shfl_sync(0xffffffffu, myi, j + 0);
            int s1 = __shfl_sync(0xffffffffu, myi, j + 1);
            int s2 = __shfl_sync(0xffffffffu, myi, j + 2);
            int s3 = __shfl_sync(0xffffffffu, myi, j + 3);
            int s4 = __shfl_sync(0xffffffffu, myi, j + 4);
            int s5 = __shfl_sync(0xffffffffu, myi, j + 5);
            int s6 = __shfl_sync(0xffffffffu, myi, j + 6);
            int s7 = __shfl_sync(0xffffffffu, myi, j + 7);
            float4 x0 = ((const float4*)(table + (size_t)s0 * D))[lane];
            float4 x1 = ((const float4*)(table + (size_t)s1 * D))[lane];
            float4 x2 = ((const float4*)(table + (size_t)s2 * D))[lane];
            float4 x3 = ((const float4*)(table + (size_t)s3 * D))[lane];
            float4 x4 = ((const float4*)(table + (size_t)s4 * D))[lane];
            float4 x5 = ((const float4*)(table + (size_t)s5 * D))[lane];
            float4 x6 = ((const float4*)(table + (size_t)s6 * D))[lane];
            float4 x7 = ((const float4*)(table + (size_t)s7 * D))[lane];
            a.x += ((x0.x + x1.x) + (x2.x + x3.x)) + ((x4.x + x5.x) + (x6.x + x7.x));
            a.y += ((x0.y + x1.y) + (x2.y + x3.y)) + ((x4.y + x5.y) + (x6.y + x7.y));
            a.z += ((x0.z + x1.z) + (x2.z + x3.z)) + ((x4.z + x5.z) + (x6.z + x7.z));
            a.w += ((x0.w + x1.w) + (x2.w + x3.w)) + ((x4.w + x5.w) + (x6.w + x7.w));
        }
        for (; j < n; j++) {
            int s = __shfl_sync(0xffffffffu, myi, j);
            float4 x = ((const float4*)(table + (size_t)s * D))[lane];
            a.x += x.x; a.y += x.y; a.z += x.z; a.w += x.w;
        }
    }
    float inv = 1.f / fmaxf((float)deg, 1.f);
    a.x *= inv; a.y *= inv; a.z *= inv; a.w *= inv;
    ((float4*)dstv)[lane] = a;
}

__global__ __launch_bounds__(256) void k_agg1(const float* __restrict__ feat) {
    int row  = (blockIdx.x * blockDim.x + threadIdx.x) >> 5;
    int lane = threadIdx.x & 31;
    if (row < NU) agg_row(feat, row, lane, g_hn + (size_t)row * D);
}

__global__ __launch_bounds__(256) void k_agg2(const int* __restrict__ users) {
    int b    = (blockIdx.x * blockDim.x + threadIdx.x) >> 5;
    int lane = threadIdx.x & 31;
    if (b < NB) agg_row(g_h1, users[b], lane, g_hn2 + (size_t)b * D);
}

// ================= split-bf16 mma.sync dense layer 1 =================
// weight prep: fp32 [k][n] -> bf16 hi/lo [n][k] (transposed for B operand)
__global__ void k_prep_w(const float* __restrict__ Ws, const float* __restrict__ Wn) {
    int i = blockIdx.x * blockDim.x + threadIdx.x;
    if (i < 4 * 16384) {
        int part = i >> 14, rem = i & 16383;
        int n = rem >> 7, k = rem & 127;
        float v = (part < 2 ? Ws : Wn)[k * 128 + n];
        __nv_bfloat16 hi = __float2bfloat16(v);
        g_wq[i] = (part & 1) ? __float2bfloat16(v - __bfloat162float(hi)) : hi;
    }
}

// SMEM layout (bytes):
//  sA  @0:        4 tiles x 64 rows x 136 bf16  (Xhi,Xlo,Hhi,Hlo)  = 69632
//  sB  @69632:    4 tiles x 128 rows x 136 bf16 (Wshi,Wslo,Wnhi,Wnlo) = 139264
//  bias@208896:   128 f32
#define W_PAD   136
#define SA_TILE (64 * W_PAD)
#define SB_TILE (128 * W_PAD)
#define OFF_B    (4 * SA_TILE * 2)
#define OFF_BIAS (OFF_B + 4 * SB_TILE * 2)
#define D1_SMEM  (OFF_BIAS + 512)     // 209408 B

__global__ __launch_bounds__(256, 1) void k_dense1_mma(
    const float* __restrict__ feat, const float* __restrict__ bias)
{
    extern __shared__ char smem[];
    __nv_bfloat16* sA = (__nv_bfloat16*)smem;
    __nv_bfloat16* sB = (__nv_bfloat16*)(smem + OFF_B);
    float* sBias = (float*)(smem + OFF_BIAS);
    const int tid = threadIdx.x, warp = tid >> 5, lane = tid & 31;
    const int r0 = blockIdx.x * 64;

    // stage A: X & H rows split hi/lo
    for (int i = tid; i < 64 * 128; i += 256) {
        int m = i >> 7, k = i & 127;
        int row = r0 + m;
        float xv = 0.f, hv = 0.f;
        if (row < NU) { xv = feat[(size_t)row * D + k]; hv = g_hn[(size_t)row * D + k]; }
        __nv_bfloat16 xh = __float2bfloat16(xv);
        __nv_bfloat16 xl = __float2bfloat16(xv - __bfloat162float(xh));
        __nv_bfloat16 hh = __float2bfloat16(hv);
        __nv_bfloat16 hl = __float2bfloat16(hv - __bfloat162float(hh));
        int o = m * W_PAD + k;
        sA[0 * SA_TILE + o] = xh; sA[1 * SA_TILE + o] = xl;
        sA[2 * SA_TILE + o] = hh; sA[3 * SA_TILE + o] = hl;
    }
    // stage B: copy prepped bf16 weights (pad to 136 stride)
    for (int i = tid; i < 4 * 16384; i += 256) {
        int part = i >> 14, rem = i & 16383, n = rem >> 7, k = rem & 127;
        sB[part * SB_TILE + n * W_PAD + k] = g_wq[i];
    }
    if (tid < 128) sBias[tid] = bias[tid];
    __syncthreads();

    // warp tile: m-tile (warp&3)*16 rows, n-half (warp>>2)*64 cols
    const int m0 = (warp & 3) * 16, n0 = (warp >> 2) * 64;
    float acc[8][4];
#pragma unroll
    for (int nt = 0; nt < 8; nt++) { acc[nt][0] = acc[nt][1] = acc[nt][2] = acc[nt][3] = 0.f; }

    const uint32_t sAb = smem_u32(smem);
    const uint32_t sBb = sAb + OFF_B;
    const uint32_t aLane = ((uint32_t)((m0 + (lane & 15)) * W_PAD + ((lane >> 4) << 3))) * 2u;
    const uint32_t bLane = ((uint32_t)((n0 + (lane & 7)) * W_PAD + (((lane >> 3) & 1) << 3))) * 2u;

    const int pa[6] = {0, 0, 1, 2, 2, 3};   // hi*hi, hi*lo, lo*hi for X@Ws then H@Wn
    const int pb[6] = {0, 1, 0, 2, 3, 2};
#pragma unroll
    for (int p = 0; p < 6; p++) {
        uint32_t Ab = sAb + pa[p] * (SA_TILE * 2) + aLane;
        uint32_t Bb = sBb + pb[p] * (SB_TILE * 2) + bLane;
        uint32_t afr[8][4];
#pragma unroll
        for (int ks = 0; ks < 8; ks++) ldsm_x4(afr[ks], Ab + ks * 32);
#pragma unroll
        for (int nt = 0; nt < 8; nt++) {
            uint32_t Bnt = Bb + nt * (8 * W_PAD * 2);
#pragma unroll
            for (int ks = 0; ks < 8; ks++) {
                uint32_t bfr[2];
                ldsm_x2(bfr, Bnt + ks * 32);
                mma_bf16(acc[nt], afr[ks], bfr);
            }
        }
    }
    __syncthreads();   // everyone done reading sA/sB

    // frags (+bias, lrelu) -> sOut[64][132] f32 (reuses sA region)
    float* sOut = (float*)smem;
#pragma unroll
    for (int nt = 0; nt < 8; nt++) {
        int col = n0 + nt * 8 + (lane & 3) * 2;
        int rA = m0 + (lane >> 2), rB = rA + 8;
        float b0v = sBias[col], b1v = sBias[col + 1];
        float v0 = acc[nt][0] + b0v; v0 = v0 > 0.f ? v0 : 0.2f * v0;
        float v1 = acc[nt][1] + b1v; v1 = v1 > 0.f ? v1 : 0.2f * v1;
        float v2 = acc[nt][2] + b0v; v2 = v2 > 0.f ? v2 : 0.2f * v2;
        float v3 = acc[nt][3] + b1v; v3 = v3 > 0.f ? v3 : 0.2f * v3;
        sOut[rA * 132 + col] = v0; sOut[rA * 132 + col + 1] = v1;
        sOut[rB * 132 + col] = v2; sOut[rB * 132 + col + 1] = v3;
    }
    __syncthreads();

    // l2-normalize rows: warp handles rows warp*8 .. +7
#pragma unroll
    for (int rr = 0; rr < 8; rr++) {
        int m = warp * 8 + rr;
        float4 v = *(const float4*)(sOut + m * 132 + lane * 4);
        float ss = v.x * v.x + v.y * v.y + v.z * v.z + v.w * v.w;
#pragma unroll
        for (int off = 16; off; off >>= 1) ss += __shfl_xor_sync(0xffffffffu, ss, off);
        float sc = 1.f / fmaxf(sqrtf(ss), 1e-12f);
        int row = r0 + m;
        if (row < NU)
            ((float4*)(g_h1 + (size_t)row * D))[lane] =
                make_float4(v.x * sc, v.y * sc, v.z * sc, v.w * sc);
    }
}

// ---------------- FFMA2 GEMM cores (dense2 / items) ----------------
__device__ __forceinline__ void gemm_dual8(
    const float* sX, const float* sH, const float* sWs, const float* sWn,
    int lr0, int lane, u64* acc0, u64* acc1)
{
#pragma unroll
    for (int j = 0; j < 8; j++) { acc0[j] = 0ull; acc1[j] = 0ull; }
#pragma unroll 4
    for (int k = 0; k < D; k += 2) {
        ulonglong2 wsa = *(const ulonglong2*)(sWs + k * D + lane * 4);
        ulonglong2 wsb = *(const ulonglong2*)(sWs + (k + 1) * D + lane * 4);
        ulonglong2 wna = *(const ulonglong2*)(sWn + k * D + lane * 4);
        ulonglong2 wnb = *(const ulonglong2*)(sWn + (k + 1) * D + lane * 4);
#pragma unroll
        for (int j = 0; j < 8; j++) {
            float2 x2 = *(const float2*)(sX + (lr0 + j) * D + k);
            float2 h2 = *(const float2*)(sH + (lr0 + j) * D + k);
            u64 xx0 = dup2(x2.x), xx1 = dup2(x2.y);
            u64 hh0 = dup2(h2.x), hh1 = dup2(h2.y);
            ffma2(acc0[j], xx0, wsa.x); ffma2(acc1[j], xx0, wsa.y);
            ffma2(acc0[j], hh0, wna.x); ffma2(acc1[j], hh0, wna.y);
            ffma2(acc0[j], xx1, wsb.x); ffma2(acc1[j], xx1, wsb.y);
            ffma2(acc0[j], hh1, wnb.x); ffma2(acc1[j], hh1, wnb.y);
        }
    }
}

__device__ __forceinline__ void gemm_one8(
    const float* sX, const float* sW, int lr0, int lane, u64* acc0, u64* acc1)
{
#pragma unroll
    for (int j = 0; j < 8; j++) { acc0[j] = 0ull; acc1[j] = 0ull; }
#pragma unroll 4
    for (int k = 0; k < D; k += 2) {
        ulonglong2 wa = *(const ulonglong2*)(sW + k * D + lane * 4);
        ulonglong2 wb = *(const ulonglong2*)(sW + (k + 1) * D + lane * 4);
#pragma unroll
        for (int j = 0; j < 8; j++) {
            float2 x2 = *(const float2*)(sX + (lr0 + j) * D + k);
            u64 xx0 = dup2(x2.x), xx1 = dup2(x2.y);
            ffma2(acc0[j], xx0, wa.x); ffma2(acc1[j], xx0, wa.y);
            ffma2(acc0[j], xx1, wb.x); ffma2(acc1[j], xx1, wb.y);
        }
    }
}

__device__ __forceinline__ float epi4(u64 a0, u64 a1, float4 b4, float4& v) {
    float2 p01 = unpk(a0), p23 = unpk(a1);
    float t0 = p01.x + b4.x, t1 = p01.y + b4.y;
    float t2 = p23.x + b4.z, t3 = p23.y + b4.w;
    t0 = t0 > 0.f ? t0 : 0.2f * t0;
    t1 = t1 > 0.f ? t1 : 0.2f * t1;
    t2 = t2 > 0.f ? t2 : 0.2f * t2;
    t3 = t3 > 0.f ? t3 : 0.2f * t3;
    v = make_float4(t0, t1, t2, t3);
    return t0 * t0 + t1 * t1 + t2 * t2 + t3 * t3;
}

// ---------------- dense SAGE layer 2 (selected users only) ----------------
__global__ __launch_bounds__(256, 1) void k_dense2(
    const float* __restrict__ ufeat, const int* __restrict__ users,
    const float* __restrict__ Ws, const float* __restrict__ Wn,
    const float* __restrict__ bias, float* __restrict__ out)
{
    extern __shared__ float sm[];
    float* sWs = sm;
    float* sWn = sm + 16384;
    float* sB  = sm + 32768;
    float* sX  = sm + 32896;
    float* sH  = sm + 32896 + 64 * D;
    const int tid = threadIdx.x;
    {
        const float4* g0 = (const float4*)Ws;
        const float4* g1 = (const float4*)Wn;
        float4* s0 = (float4*)sWs;
        float4* s1 = (float4*)sWn;
        for (int i = tid; i < 4096; i += 256) { s0[i] = g0[i]; s1[i] = g1[i]; }
        if (tid < 32) ((float4*)sB)[tid] = ((const float4*)bias)[tid];
    }
    const int warp = tid >> 5, lane = tid & 31;
    const int lr0 = warp * 8;
    const int r0 = blockIdx.x * 64;
#pragma unroll
    for (int j = 0; j < 8; j++) {
        int b = r0 + lr0 + j;
        int u = users[b];
        float4 x4 = ((const float4*)(g_h1 + (size_t)u * D))[lane];
        ((float4*)(sX + (lr0 + j) * D))[lane] = x4;
        ((float4*)(sH + (lr0 + j) * D))[lane] =
            ((const float4*)(g_hn2 + (size_t)b * D))[lane];
        ((float4*)(out + (size_t)b * 384))[lane]       = ((const float4*)(ufeat + (size_t)u * D))[lane];
        ((float4*)(out + (size_t)b * 384 + 128))[lane] = x4;
    }
    __syncthreads();

    u64 acc0[8], acc1[8];
    gemm_dual8(sX, sH, sWs, sWn, lr0, lane, acc0, acc1);

    float4 b4 = ((const float4*)sB)[lane];
    float4 v[8]; float ss[8];
#pragma unroll
    for (int j = 0; j < 8; j++) ss[j] = epi4(acc0[j], acc1[j], b4, v[j]);
#pragma unroll
    for (int off = 16; off; off >>= 1) {
#pragma unroll
        for (int j = 0; j < 8; j++) ss[j] += __shfl_xor_sync(0xffffffffu, ss[j], off);
    }
#pragma unroll
    for (int j = 0; j < 8; j++) {
        float sc = 1.f / fmaxf(sqrtf(ss[j]), 1e-12f);
        int b = r0 + lr0 + j;
        ((float4*)(out + (size_t)b * 384 + 256))[lane] =
            make_float4(v[j].x * sc, v[j].y * sc, v[j].z * sc, v[j].w * sc);
    }
}

// ---------------- item tower (gathered rows only) ----------------
__global__ __launch_bounds__(256, 1) void k_items(
    const float* __restrict__ ifeat, const int* __restrict__ pos, const int* __restrict__ neg,
    const float* __restrict__ W0, const float* __restrict__ b0,
    const float* __restrict__ W1, const float* __restrict__ b1,
    float* __restrict__ out)
{
    extern __shared__ float sm[];
    float* sW0 = sm;
    float* sW1 = sm + 16384;
    float* sB0 = sm + 32768;
    float* sB1 = sm + 32896;
    float* sX  = sm + 33024;
    const int tid = threadIdx.x;
    {
        const float4* g0 = (const float4*)W0;
        const float4* g1 = (const float4*)W1;
        float4* s0 = (float4*)sW0;
        float4* s1 = (float4*)sW1;
        for (int i = tid; i < 4096; i += 256) { s0[i] = g0[i]; s1[i] = g1[i]; }
        if (tid < 32) {
            ((float4*)sB0)[tid] = ((const float4*)b0)[tid];
            ((float4*)sB1)[tid] = ((const float4*)b1)[tid];
        }
    }
    const int warp = tid >> 5, lane = tid & 31;
    const int lr0 = warp * 8;
    const int r0 = blockIdx.x * 64;
#pragma unroll
    for (int j = 0; j < 8; j++) {
        int rr = r0 + lr0 + j;
        int idx = (rr < NB) ? pos[rr] : neg[rr - NB];
        float4 x4 = ((const float4*)(ifeat + (size_t)idx * D))[lane];
        ((float4*)(sX + (lr0 + j) * D))[lane] = x4;
        ((float4*)(out + (size_t)(NB + rr) * 384))[lane] = x4;
    }
    __syncthreads();

    u64 acc0[8], acc1[8];
    gemm_one8(sX, sW0, lr0, lane, acc0, acc1);
    {
        float4 b4 = ((const float4*)sB0)[lane];
        float4 v[8]; float ss[8];
#pragma unroll
        for (int j = 0; j < 8; j++) ss[j] = epi4(acc0[j], acc1[j], b4, v[j]);
#pragma unroll
        for (int off = 16; off; off >>= 1) {
#pragma unroll
            for (int j = 0; j < 8; j++) ss[j] += __shfl_xor_sync(0xffffffffu, ss[j], off);
        }
        __syncwarp();
#pragma unroll
        for (int j = 0; j < 8; j++) {
            float sc = 1.f / fmaxf(sqrtf(ss[j]), 1e-12f);
            float4 o = make_float4(v[j].x * sc, v[j].y * sc, v[j].z * sc, v[j].w * sc);
            int rr = r0 + lr0 + j;
            ((float4*)(sX + (lr0 + j) * D))[lane] = o;
            ((float4*)(out + (size_t)(NB + rr) * 384 + 128))[lane] = o;
        }
        __syncwarp();
    }

    gemm_one8(sX, sW1, lr0, lane, acc0, acc1);
    {
        float4 b4 = ((const float4*)sB1)[lane];
        float4 v[8]; float ss[8];
#pragma unroll
        for (int j = 0; j < 8; j++) ss[j] = epi4(acc0[j], acc1[j], b4, v[j]);
#pragma unroll
        for (int off = 16; off; off >>= 1) {
#pragma unroll
            for (int j = 0; j < 8; j++) ss[j] += __shfl_xor_sync(0xffffffffu, ss[j], off);
        }
#pragma unroll
        for (int j = 0; j < 8; j++) {
            float sc = 1.f / fmaxf(sqrtf(ss[j]), 1e-12f);
            int rr = r0 + lr0 + j;
            ((float4*)(out + (size_t)(NB + rr) * 384 + 256))[lane] =
                make_float4(v[j].x * sc, v[j].y * sc, v[j].z * sc, v[j].w * sc);
        }
    }
}

// ---------------- launch ----------------
extern "C" void kernel_launch(void* const* d_in, const int* in_sizes, int n_in,
                              void* d_out, int out_size) {
    const int*   src   = (const int*)d_in[0];
    const int*   dst   = (const int*)d_in[1];
    const int*   users = (const int*)d_in[2];
    const int*   pos   = (const int*)d_in[3];
    const int*   neg   = (const int*)d_in[4];
    const float* ufeat = (const float*)d_in[5];
    const float* ifeat = (const float*)d_in[6];
    const float* Ws0   = (const float*)d_in[7];
    const float* Wn0   = (const float*)d_in[8];
    const float* bu0   = (const float*)d_in[9];
    const float* Wi0   = (const float*)d_in[10];
    const float* bi0   = (const float*)d_in[11];
    const float* Ws1   = (const float*)d_in[12];
    const float* Wn1   = (const float*)d_in[13];
    const float* bu1   = (const float*)d_in[14];
    const float* Wi1   = (const float*)d_in[15];
    const float* bi1   = (const float*)d_in[16];
    float* out = (float*)d_out;

    const int sm_dense = (16384 * 2 + 128 + 64 * D * 2) * sizeof(float);
    const int sm_items = (16384 * 2 + 256 + 64 * D) * sizeof(float);
    (void)cudaFuncSetAttribute(k_dense1_mma, cudaFuncAttributeMaxDynamicSharedMemorySize, D1_SMEM);
    (void)cudaFuncSetAttribute(k_dense2, cudaFuncAttributeMaxDynamicSharedMemorySize, sm_dense);
    (void)cudaFuncSetAttribute(k_items,  cudaFuncAttributeMaxDynamicSharedMemorySize, sm_items);

    // launch order puts k_items at index 3 (the launch ncu -s5 -c1 captures)
    k_prep_w    <<<(4 * 16384) / 256, 256>>>(Ws0, Wn0);
    k_zero      <<<(NU + 255) / 256, 256>>>();
    k_count     <<<(NE / 8 + 255) / 256, 256>>>(dst);
    k_items     <<<(2 * NB) / 64, 256, sm_items>>>(ifeat, pos, neg, Wi0, bi0, Wi1, bi1, out);
    k_scan_local<<<SCAN_B, 1024>>>();
    k_scan_top  <<<1, 128>>>();
    k_scan_add  <<<(NU + 255) / 256, 256>>>();
    k_scatter   <<<(NE / 8 + 255) / 256, 256>>>(src, dst);

    // user tower
    k_agg1      <<<(NU * 32 + 255) / 256, 256>>>(ufeat);
    k_dense1_mma<<<(NU + 63) / 64, 256, D1_SMEM>>>(ufeat, bu0);
    k_agg2      <<<(NB * 32) / 256, 256>>>(users);
    k_dense2    <<<NB / 64, 256, sm_dense>>>(ufeat, users, Ws1, Wn1, bu1, out);
}

// round 9
// speedup vs baseline: 1.2655x; 1.2655x over previous
#include <cuda_runtime.h>
#include <cstdint>

#define NU 100000
#define NE 1600000
#define NB 16384
#define D  128
#define SCAN_B 98   // ceil(NU / 1024)

typedef unsigned long long u64;

// ---- static scratch (no allocations allowed) ----
static __device__ int   g_rowptr[NU + 1];
static __device__ int   g_cursor[NU];
static __device__ int   g_esrc[NE];
static __device__ int   g_bsum[SCAN_B];
static __device__ int   g_boff[SCAN_B];
static __device__ float g_h1 [(size_t)NU * D];   // layer-1 user output
static __device__ float g_hn [(size_t)NU * D];   // layer-1 neighbor mean
static __device__ float g_hn2[(size_t)NB * D];   // layer-2 neighbor mean
static __device__ float g_acc[(size_t)NU * D];   // partial-GEMM accumulator
static __device__ float g_hi [(size_t)(2 * NB) * D];  // item layer-1 output

// ---------------- packed f32x2 helpers ----------------
__device__ __forceinline__ u64 dup2(float x) {
    u64 r; asm("mov.b64 %0, {%1, %1};" : "=l"(r) : "f"(x)); return r;
}
__device__ __forceinline__ void ffma2(u64& d, u64 a, u64 b) {
    asm("fma.rn.f32x2 %0, %1, %2, %0;" : "+l"(d) : "l"(a), "l"(b));
}
__device__ __forceinline__ float2 unpk(u64 v) {
    float2 r; asm("mov.b64 {%0, %1}, %2;" : "=f"(r.x), "=f"(r.y) : "l"(v)); return r;
}

// ---------------- CSR build ----------------
__global__ void k_zero() {
    int i = blockIdx.x * blockDim.x + threadIdx.x;
    if (i < NU) g_cursor[i] = 0;
}

__global__ void k_count(const int* __restrict__ dst) {
    int i = blockIdx.x * blockDim.x + threadIdx.x;
    if (i < NE / 8) {
        int4 d0 = ((const int4*)dst)[2 * i];
        int4 d1 = ((const int4*)dst)[2 * i + 1];
        atomicAdd(&g_cursor[d0.x], 1); atomicAdd(&g_cursor[d0.y], 1);
        atomicAdd(&g_cursor[d0.z], 1); atomicAdd(&g_cursor[d0.w], 1);
        atomicAdd(&g_cursor[d1.x], 1); atomicAdd(&g_cursor[d1.y], 1);
        atomicAdd(&g_cursor[d1.z], 1); atomicAdd(&g_cursor[d1.w], 1);
    }
}

__global__ __launch_bounds__(1024) void k_scan_local() {
    __shared__ int sh[1024];
    const int t = threadIdx.x;
    const int i = blockIdx.x * 1024 + t;
    int c = (i < NU) ? g_cursor[i] : 0;
    int val = c;
    sh[t] = val;
    __syncthreads();
#pragma unroll
    for (int off = 1; off < 1024; off <<= 1) {
        int tmp = (t >= off) ? sh[t - off] : 0;
        __syncthreads();
        val += tmp;
        sh[t] = val;
        __syncthreads();
    }
    if (i < NU) g_rowptr[i] = val - c;
    if (t == 1023) g_bsum[blockIdx.x] = val;
}

__global__ __launch_bounds__(128) void k_scan_top() {
    __shared__ int sh[128];
    const int t = threadIdx.x;
    int v = (t < SCAN_B) ? g_bsum[t] : 0;
    int val = v;
    sh[t] = val;
    __syncthreads();
#pragma unroll
    for (int off = 1; off < 128; off <<= 1) {
        int tmp = (t >= off) ? sh[t - off] : 0;
        __syncthreads();
        val += tmp;
        sh[t] = val;
        __syncthreads();
    }
    if (t < SCAN_B) g_boff[t] = val - v;
}

__global__ void k_scan_add() {
    int i = blockIdx.x * blockDim.x + threadIdx.x;
    if (i < NU) {
        int r = g_rowptr[i] + g_boff[i >> 10];
        g_rowptr[i] = r;
        g_cursor[i] = r;
    }
    if (i == 0) g_rowptr[NU] = NE;
}

__global__ void k_scatter(const int* __restrict__ src, const int* __restrict__ dst) {
    int i = blockIdx.x * blockDim.x + threadIdx.x;
    if (i < NE / 8) {
        int4 d0 = ((const int4*)dst)[2 * i];
        int4 d1 = ((const int4*)dst)[2 * i + 1];
        int4 s0 = ((const int4*)src)[2 * i];
        int4 s1 = ((const int4*)src)[2 * i + 1];
        int p0 = atomicAdd(&g_cursor[d0.x], 1);
        int p1 = atomicAdd(&g_cursor[d0.y], 1);
        int p2 = atomicAdd(&g_cursor[d0.z], 1);
        int p3 = atomicAdd(&g_cursor[d0.w], 1);
        int p4 = atomicAdd(&g_cursor[d1.x], 1);
        int p5 = atomicAdd(&g_cursor[d1.y], 1);
        int p6 = atomicAdd(&g_cursor[d1.z], 1);
        int p7 = atomicAdd(&g_cursor[d1.w], 1);
        g_esrc[p0] = s0.x; g_esrc[p1] = s0.y; g_esrc[p2] = s0.z; g_esrc[p3] = s0.w;
        g_esrc[p4] = s1.x; g_esrc[p5] = s1.y; g_esrc[p6] = s1.z; g_esrc[p7] = s1.w;
    }
}

// ---------------- high-occupancy neighbor-mean aggregation ----------------
__device__ __forceinline__ void agg_row(
    const float* __restrict__ table, int row, int lane, float* __restrict__ dstv)
{
    int beg = g_rowptr[row], end = g_rowptr[row + 1];
    int deg = end - beg;
    float4 a = make_float4(0.f, 0.f, 0.f, 0.f);
    for (int base = 0; base < deg; base += 32) {
        int rem = deg - base;
        int n = rem < 32 ? rem : 32;
        int myi = (lane < n) ? g_esrc[beg + base + lane] : 0;
        int j = 0;
        for (; j + 8 <= n; j += 8) {
            int s0 = __shfl_sync(0xffffffffu, myi, j + 0);
            int s1 = __shfl_sync(0xffffffffu, myi, j + 1);
            int s2 = __shfl_sync(0xffffffffu, myi, j + 2);
            int s3 = __shfl_sync(0xffffffffu, myi, j + 3);
            int s4 = __shfl_sync(0xffffffffu, myi, j + 4);
            int s5 = __shfl_sync(0xffffffffu, myi, j + 5);
            int s6 = __shfl_sync(0xffffffffu, myi, j + 6);
            int s7 = __shfl_sync(0xffffffffu, myi, j + 7);
            float4 x0 = ((const float4*)(table + (size_t)s0 * D))[lane];
            float4 x1 = ((const float4*)(table + (size_t)s1 * D))[lane];
            float4 x2 = ((const float4*)(table + (size_t)s2 * D))[lane];
            float4 x3 = ((const float4*)(table + (size_t)s3 * D))[lane];
            float4 x4 = ((const float4*)(table + (size_t)s4 * D))[lane];
            float4 x5 = ((const float4*)(table + (size_t)s5 * D))[lane];
            float4 x6 = ((const float4*)(table + (size_t)s6 * D))[lane];
            float4 x7 = ((const float4*)(table + (size_t)s7 * D))[lane];
            a.x += ((x0.x + x1.x) + (x2.x + x3.x)) + ((x4.x + x5.x) + (x6.x + x7.x));
            a.y += ((x0.y + x1.y) + (x2.y + x3.y)) + ((x4.y + x5.y) + (x6.y + x7.y));
            a.z += ((x0.z + x1.z) + (x2.z + x3.z)) + ((x4.z + x5.z) + (x6.z + x7.z));
            a.w += ((x0.w + x1.w) + (x2.w + x3.w)) + ((x4.w + x5.w) + (x6.w + x7.w));
        }
        for (; j < n; j++) {
            int s = __shfl_sync(0xffffffffu, myi, j);
            float4 x = ((const float4*)(table + (size_t)s * D))[lane];
            a.x += x.x; a.y += x.y; a.z += x.z; a.w += x.w;
        }
    }
    float inv = 1.f / fmaxf((float)deg, 1.f);
    a.x *= inv; a.y *= inv; a.z *= inv; a.w *= inv;
    ((float4*)dstv)[lane] = a;
}

__global__ __launch_bounds__(256) void k_agg1(const float* __restrict__ feat) {
    int row  = (blockIdx.x * blockDim.x + threadIdx.x) >> 5;
    int lane = threadIdx.x & 31;
    if (row < NU) agg_row(feat, row, lane, g_hn + (size_t)row * D);
}

__global__ __launch_bounds__(256) void k_agg2(const int* __restrict__ users) {
    int b    = (blockIdx.x * blockDim.x + threadIdx.x) >> 5;
    int lane = threadIdx.x & 31;
    if (b < NB) agg_row(g_h1, users[b], lane, g_hn2 + (size_t)b * D);
}

// ---------------- FFMA2 single-weight GEMM core ----------------
// smem layout (floats): sW[16384], sB[128], sX[64*128]  = 98816 bytes
#define GM_SMEM ((16384 + 128 + 64 * D) * (int)sizeof(float))

__device__ __forceinline__ void gemm_one8(
    const float* sX, const float* sW, int lr0, int lane, u64* acc0, u64* acc1)
{
#pragma unroll
    for (int j = 0; j < 8; j++) { acc0[j] = 0ull; acc1[j] = 0ull; }
#pragma unroll 4
    for (int k = 0; k < D; k += 2) {
        ulonglong2 wa = *(const ulonglong2*)(sW + k * D + lane * 4);
        ulonglong2 wb = *(const ulonglong2*)(sW + (k + 1) * D + lane * 4);
#pragma unroll
        for (int j = 0; j < 8; j++) {
            float2 x2 = *(const float2*)(sX + (lr0 + j) * D + k);
            u64 xx0 = dup2(x2.x), xx1 = dup2(x2.y);
            ffma2(acc0[j], xx0, wa.x); ffma2(acc1[j], xx0, wa.y);
            ffma2(acc0[j], xx1, wb.x); ffma2(acc1[j], xx1, wb.y);
        }
    }
}

__device__ __forceinline__ void stage_w(const float* __restrict__ W, float* sW, int tid) {
    const float4* g = (const float4*)W;
    float4* s = (float4*)sW;
    for (int i = tid; i < 4096; i += 256) s[i] = g[i];
}

__device__ __forceinline__ float epi4(u64 a0, u64 a1, float4 pa, float4 b4, float4& v) {
    float2 p01 = unpk(a0), p23 = unpk(a1);
    float t0 = p01.x + pa.x + b4.x, t1 = p01.y + pa.y + b4.y;
    float t2 = p23.x + pa.z + b4.z, t3 = p23.y + pa.w + b4.w;
    t0 = t0 > 0.f ? t0 : 0.2f * t0;
    t1 = t1 > 0.f ? t1 : 0.2f * t1;
    t2 = t2 > 0.f ? t2 : 0.2f * t2;
    t3 = t3 > 0.f ? t3 : 0.2f * t3;
    v = make_float4(t0, t1, t2, t3);
    return t0 * t0 + t1 * t1 + t2 * t2 + t3 * t3;
}

// ---------------- dense1 pass A: g_acc = feat @ Ws ----------------
__global__ __launch_bounds__(256, 2) void k_d1a(
    const float* __restrict__ feat, const float* __restrict__ Ws)
{
    extern __shared__ float sm[];
    float* sW = sm;
    float* sX = sm + 16384 + 128;
    const int tid = threadIdx.x, warp = tid >> 5, lane = tid & 31;
    stage_w(Ws, sW, tid);
    const int lr0 = warp * 8;
    const int r0 = blockIdx.x * 64;
#pragma unroll
    for (int j = 0; j < 8; j++) {
        int row = r0 + lr0 + j;
        ((float4*)(sX + (lr0 + j) * D))[lane] = (row < NU)
            ? ((const float4*)(feat + (size_t)row * D))[lane]
            : make_float4(0.f, 0.f, 0.f, 0.f);
    }
    __syncthreads();
    u64 acc0[8], acc1[8];
    gemm_one8(sX, sW, lr0, lane, acc0, acc1);
#pragma unroll
    for (int j = 0; j < 8; j++) {
        int row = r0 + lr0 + j;
        if (row < NU) {
            float2 p01 = unpk(acc0[j]), p23 = unpk(acc1[j]);
            ((float4*)(g_acc + (size_t)row * D))[lane] =
                make_float4(p01.x, p01.y, p23.x, p23.y);
        }
    }
}

// ---------------- dense1 pass B: g_h1 = l2n(lrelu(g_acc + g_hn @ Wn + b)) ----------------
__global__ __launch_bounds__(256, 2) void k_d1b(
    const float* __restrict__ Wn, const float* __restrict__ bias)
{
    extern __shared__ float sm[];
    float* sW = sm;
    float* sB = sm + 16384;
    float* sX = sm + 16384 + 128;
    const int tid = threadIdx.x, warp = tid >> 5, lane = tid & 31;
    stage_w(Wn, sW, tid);
    if (tid < 32) ((float4*)sB)[tid] = ((const float4*)bias)[tid];
    const int lr0 = warp * 8;
    const int r0 = blockIdx.x * 64;
#pragma unroll
    for (int j = 0; j < 8; j++) {
        int row = r0 + lr0 + j;
        ((float4*)(sX + (lr0 + j) * D))[lane] = (row < NU)
            ? ((const float4*)(g_hn + (size_t)row * D))[lane]
            : make_float4(0.f, 0.f, 0.f, 0.f);
    }
    __syncthreads();
    u64 acc0[8], acc1[8];
    gemm_one8(sX, sW, lr0, lane, acc0, acc1);

    float4 b4 = ((const float4*)sB)[lane];
    float4 v[8]; float ss[8];
#pragma unroll
    for (int j = 0; j < 8; j++) {
        int row = r0 + lr0 + j;
        float4 pa = (row < NU) ? ((const float4*)(g_acc + (size_t)row * D))[lane]
                               : make_float4(0.f, 0.f, 0.f, 0.f);
        ss[j] = epi4(acc0[j], acc1[j], pa, b4, v[j]);
    }
#pragma unroll
    for (int off = 16; off; off >>= 1) {
#pragma unroll
        for (int j = 0; j < 8; j++) ss[j] += __shfl_xor_sync(0xffffffffu, ss[j], off);
    }
#pragma unroll
    for (int j = 0; j < 8; j++) {
        int row = r0 + lr0 + j;
        if (row < NU) {
            float sc = 1.f / fmaxf(sqrtf(ss[j]), 1e-12f);
            ((float4*)(g_h1 + (size_t)row * D))[lane] =
                make_float4(v[j].x * sc, v[j].y * sc, v[j].z * sc, v[j].w * sc);
        }
    }
}

// ---------------- dense2 pass A ----------------
__global__ __launch_bounds__(256, 2) void k_d2a(
    const float* __restrict__ ufeat, const int* __restrict__ users,
    const float* __restrict__ Ws, float* __restrict__ out)
{
    extern __shared__ float sm[];
    float* sW = sm;
    float* sX = sm + 16384 + 128;
    const int tid = threadIdx.x, warp = tid >> 5, lane = tid & 31;
    stage_w(Ws, sW, tid);
    const int lr0 = warp * 8;
    const int r0 = blockIdx.x * 64;     // NB % 64 == 0
#pragma unroll
    for (int j = 0; j < 8; j++) {
        int b = r0 + lr0 + j;
        int u = users[b];
        float4 x4 = ((const float4*)(g_h1 + (size_t)u * D))[lane];
        ((float4*)(sX + (lr0 + j) * D))[lane] = x4;
        ((float4*)(out + (size_t)b * 384))[lane]       = ((const float4*)(ufeat + (size_t)u * D))[lane];
        ((float4*)(out + (size_t)b * 384 + 128))[lane] = x4;
    }
    __syncthreads();
    u64 acc0[8], acc1[8];
    gemm_one8(sX, sW, lr0, lane, acc0, acc1);
#pragma unroll
    for (int j = 0; j < 8; j++) {
        int b = r0 + lr0 + j;
        float2 p01 = unpk(acc0[j]), p23 = unpk(acc1[j]);
        ((float4*)(g_acc + (size_t)b * D))[lane] = make_float4(p01.x, p01.y, p23.x, p23.y);
    }
}

// ---------------- dense2 pass B ----------------
__global__ __launch_bounds__(256, 2) void k_d2b(
    const float* __restrict__ Wn, const float* __restrict__ bias, float* __restrict__ out)
{
    extern __shared__ float sm[];
    float* sW = sm;
    float* sB = sm + 16384;
    float* sX = sm + 16384 + 128;
    const int tid = threadIdx.x, warp = tid >> 5, lane = tid & 31;
    stage_w(Wn, sW, tid);
    if (tid < 32) ((float4*)sB)[tid] = ((const float4*)bias)[tid];
    const int lr0 = warp * 8;
    const int r0 = blockIdx.x * 64;
#pragma unroll
    for (int j = 0; j < 8; j++) {
        int b = r0 + lr0 + j;
        ((float4*)(sX + (lr0 + j) * D))[lane] =
            ((const float4*)(g_hn2 + (size_t)b * D))[lane];
    }
    __syncthreads();
    u64 acc0[8], acc1[8];
    gemm_one8(sX, sW, lr0, lane, acc0, acc1);

    float4 b4 = ((const float4*)sB)[lane];
    float4 v[8]; float ss[8];
#pragma unroll
    for (int j = 0; j < 8; j++) {
        int b = r0 + lr0 + j;
        float4 pa = ((const float4*)(g_acc + (size_t)b * D))[lane];
        ss[j] = epi4(acc0[j], acc1[j], pa, b4, v[j]);
    }
#pragma unroll
    for (int off = 16; off; off >>= 1) {
#pragma unroll
        for (int j = 0; j < 8; j++) ss[j] += __shfl_xor_sync(0xffffffffu, ss[j], off);
    }
#pragma unroll
    for (int j = 0; j < 8; j++) {
        float sc = 1.f / fmaxf(sqrtf(ss[j]), 1e-12f);
        int b = r0 + lr0 + j;
        ((float4*)(out + (size_t)b * 384 + 256))[lane] =
            make_float4(v[j].x * sc, v[j].y * sc, v[j].z * sc, v[j].w * sc);
    }
}

// ---------------- item tower pass 1 ----------------
__global__ __launch_bounds__(256, 2) void k_it1(
    const float* __restrict__ ifeat, const int* __restrict__ pos, const int* __restrict__ neg,
    const float* __restrict__ W0, const float* __restrict__ b0, float* __restrict__ out)
{
    extern __shared__ float sm[];
    float* sW = sm;
    float* sB = sm + 16384;
    float* sX = sm + 16384 + 128;
    const int tid = threadIdx.x, warp = tid >> 5, lane = tid & 31;
    stage_w(W0, sW, tid);
    if (tid < 32) ((float4*)sB)[tid] = ((const float4*)b0)[tid];
    const int lr0 = warp * 8;
    const int r0 = blockIdx.x * 64;     // 2*NB % 64 == 0
#pragma unroll
    for (int j = 0; j < 8; j++) {
        int rr = r0 + lr0 + j;
        int idx = (rr < NB) ? pos[rr] : neg[rr - NB];
        float4 x4 = ((const float4*)(ifeat + (size_t)idx * D))[lane];
        ((float4*)(sX + (lr0 + j) * D))[lane] = x4;
        ((float4*)(out + (size_t)(NB + rr) * 384))[lane] = x4;   // seg 0
    }
    __syncthreads();
    u64 acc0[8], acc1[8];
    gemm_one8(sX, sW, lr0, lane, acc0, acc1);

    float4 b4 = ((const float4*)sB)[lane];
    const float4 z4 = make_float4(0.f, 0.f, 0.f, 0.f);
    float4 v[8]; float ss[8];
#pragma unroll
    for (int j = 0; j < 8; j++) ss[j] = epi4(acc0[j], acc1[j], z4, b4, v[j]);
#pragma unroll
    for (int off = 16; off; off >>= 1) {
#pragma unroll
        for (int j = 0; j < 8; j++) ss[j] += __shfl_xor_sync(0xffffffffu, ss[j], off);
    }
#pragma unroll
    for (int j = 0; j < 8; j++) {
        float sc = 1.f / fmaxf(sqrtf(ss[j]), 1e-12f);
        int rr = r0 + lr0 + j;
        float4 o = make_float4(v[j].x * sc, v[j].y * sc, v[j].z * sc, v[j].w * sc);
        ((float4*)(g_hi + (size_t)rr * D))[lane] = o;
        ((float4*)(out + (size_t)(NB + rr) * 384 + 128))[lane] = o;  // seg 1
    }
}

// ---------------- item tower pass 2 ----------------
__global__ __launch_bounds__(256, 2) void k_it2(
    const float* __restrict__ W1, const float* __restrict__ b1, float* __restrict__ out)
{
    extern __shared__ float sm[];
    float* sW = sm;
    float* sB = sm + 16384;
    float* sX = sm + 16384 + 128;
    const int tid = threadIdx.x, warp = tid >> 5, lane = tid & 31;
    stage_w(W1, sW, tid);
    if (tid < 32) ((float4*)sB)[tid] = ((const float4*)b1)[tid];
    const int lr0 = warp * 8;
    const int r0 = blockIdx.x * 64;
#pragma unroll
    for (int j = 0; j < 8; j++) {
        int rr = r0 + lr0 + j;
        ((float4*)(sX + (lr0 + j) * D))[lane] =
            ((const float4*)(g_hi + (size_t)rr * D))[lane];
    }
    __syncthreads();
    u64 acc0[8], acc1[8];
    gemm_one8(sX, sW, lr0, lane, acc0, acc1);

    float4 b4 = ((const float4*)sB)[lane];
    const float4 z4 = make_float4(0.f, 0.f, 0.f, 0.f);
    float4 v[8]; float ss[8];
#pragma unroll
    for (int j = 0; j < 8; j++) ss[j] = epi4(acc0[j], acc1[j], z4, b4, v[j]);
#pragma unroll
    for (int off = 16; off; off >>= 1) {
#pragma unroll
        for (int j = 0; j < 8; j++) ss[j] += __shfl_xor_sync(0xffffffffu, ss[j], off);
    }
#pragma unroll
    for (int j = 0; j < 8; j++) {
        float sc = 1.f / fmaxf(sqrtf(ss[j]), 1e-12f);
        int rr = r0 + lr0 + j;
        ((float4*)(out + (size_t)(NB + rr) * 384 + 256))[lane] =
            make_float4(v[j].x * sc, v[j].y * sc, v[j].z * sc, v[j].w * sc);
    }
}

// ---------------- launch ----------------
extern "C" void kernel_launch(void* const* d_in, const int* in_sizes, int n_in,
                              void* d_out, int out_size) {
    const int*   src   = (const int*)d_in[0];
    const int*   dst   = (const int*)d_in[1];
    const int*   users = (const int*)d_in[2];
    const int*   pos   = (const int*)d_in[3];
    const int*   neg   = (const int*)d_in[4];
    const float* ufeat = (const float*)d_in[5];
    const float* ifeat = (const float*)d_in[6];
    const float* Ws0   = (const float*)d_in[7];
    const float* Wn0   = (const float*)d_in[8];
    const float* bu0   = (const float*)d_in[9];
    const float* Wi0   = (const float*)d_in[10];
    const float* bi0   = (const float*)d_in[11];
    const float* Ws1   = (const float*)d_in[12];
    const float* Wn1   = (const float*)d_in[13];
    const float* bu1   = (const float*)d_in[14];
    const float* Wi1   = (const float*)d_in[15];
    const float* bi1   = (const float*)d_in[16];
    float* out = (float*)d_out;

    (void)cudaFuncSetAttribute(k_d1a, cudaFuncAttributeMaxDynamicSharedMemorySize, GM_SMEM);
    (void)cudaFuncSetAttribute(k_d1b, cudaFuncAttributeMaxDynamicSharedMemorySize, GM_SMEM);
    (void)cudaFuncSetAttribute(k_d2a, cudaFuncAttributeMaxDynamicSharedMemorySize, GM_SMEM);
    (void)cudaFuncSetAttribute(k_d2b, cudaFuncAttributeMaxDynamicSharedMemorySize, GM_SMEM);
    (void)cudaFuncSetAttribute(k_it1, cudaFuncAttributeMaxDynamicSharedMemorySize, GM_SMEM);
    (void)cudaFuncSetAttribute(k_it2, cudaFuncAttributeMaxDynamicSharedMemorySize, GM_SMEM);

    const int GD1 = (NU + 63) / 64;     // 1563
    const int GD2 = NB / 64;            // 256
    const int GIT = (2 * NB) / 64;      // 512

    // index 3 = k_d1a (ncu -s5 -c1 captures launch #3)
    k_zero      <<<(NU + 255) / 256, 256>>>();
    k_count     <<<(NE / 8 + 255) / 256, 256>>>(dst);
    k_it1       <<<GIT, 256, GM_SMEM>>>(ifeat, pos, neg, Wi0, bi0, out);
    k_d1a       <<<GD1, 256, GM_SMEM>>>(ufeat, Ws0);
    k_scan_local<<<SCAN_B, 1024>>>();
    k_scan_top  <<<1, 128>>>();
    k_scan_add  <<<(NU + 255) / 256, 256>>>();
    k_scatter   <<<(NE / 8 + 255) / 256, 256>>>(src, dst);
    k_it2       <<<GIT, 256, GM_SMEM>>>(Wi1, bi1, out);
    k_agg1      <<<(NU * 32 + 255) / 256, 256>>>(ufeat);
    k_d1b       <<<GD1, 256, GM_SMEM>>>(Wn0, bu0);
    k_agg2      <<<(NB * 32) / 256, 256>>>(users);
    k_d2a       <<<GD2, 256, GM_SMEM>>>(ufeat, users, Ws1, out);
    k_d2b       <<<GD2, 256, GM_SMEM>>>(Wn1, bu1, out);
}

// round 10
// speedup vs baseline: 1.3746x; 1.0862x over previous
#include <cuda_runtime.h>
#include <cstdint>

#define NU 100000
#define NE 1600000
#define NB 16384
#define D  128
#define SCAN_B 98   // ceil(NU / 1024)

typedef unsigned long long u64;

// ---- static scratch (no allocations allowed) ----
static __device__ int   g_rowptr[NU + 1];
static __device__ int   g_cursor[NU];
static __device__ int   g_esrc[NE];
static __device__ int   g_bsum[SCAN_B];
static __device__ int   g_boff[SCAN_B];
static __device__ float g_h1 [(size_t)NU * D];   // layer-1 user output
static __device__ float g_hn [(size_t)NU * D];   // layer-1 neighbor mean
static __device__ float g_hn2[(size_t)NB * D];   // layer-2 neighbor mean
static __device__ float g_acc[(size_t)NU * D];   // partial-GEMM accumulator
static __device__ float g_hi [(size_t)(2 * NB) * D];  // item layer-1 output

// ---------------- packed f32x2 helpers ----------------
__device__ __forceinline__ u64 dup2(float x) {
    u64 r; asm("mov.b64 %0, {%1, %1};" : "=l"(r) : "f"(x)); return r;
}
__device__ __forceinline__ void ffma2(u64& d, u64 a, u64 b) {
    asm("fma.rn.f32x2 %0, %1, %2, %0;" : "+l"(d) : "l"(a), "l"(b));
}
__device__ __forceinline__ float2 unpk(u64 v) {
    float2 r; asm("mov.b64 {%0, %1}, %2;" : "=f"(r.x), "=f"(r.y) : "l"(v)); return r;
}

// ---------------- CSR build ----------------
__global__ void k_zero() {
    int i = blockIdx.x * blockDim.x + threadIdx.x;
    if (i < NU) g_cursor[i] = 0;
}

__global__ void k_count(const int* __restrict__ dst) {
    int i = blockIdx.x * blockDim.x + threadIdx.x;
    if (i < NE / 8) {
        int4 d0 = ((const int4*)dst)[2 * i];
        int4 d1 = ((const int4*)dst)[2 * i + 1];
        atomicAdd(&g_cursor[d0.x], 1); atomicAdd(&g_cursor[d0.y], 1);
        atomicAdd(&g_cursor[d0.z], 1); atomicAdd(&g_cursor[d0.w], 1);
        atomicAdd(&g_cursor[d1.x], 1); atomicAdd(&g_cursor[d1.y], 1);
        atomicAdd(&g_cursor[d1.z], 1); atomicAdd(&g_cursor[d1.w], 1);
    }
}

__global__ __launch_bounds__(1024) void k_scan_local() {
    __shared__ int sh[1024];
    const int t = threadIdx.x;
    const int i = blockIdx.x * 1024 + t;
    int c = (i < NU) ? g_cursor[i] : 0;
    int val = c;
    sh[t] = val;
    __syncthreads();
#pragma unroll
    for (int off = 1; off < 1024; off <<= 1) {
        int tmp = (t >= off) ? sh[t - off] : 0;
        __syncthreads();
        val += tmp;
        sh[t] = val;
        __syncthreads();
    }
    if (i < NU) g_rowptr[i] = val - c;
    if (t == 1023) g_bsum[blockIdx.x] = val;
}

__global__ __launch_bounds__(128) void k_scan_top() {
    __shared__ int sh[128];
    const int t = threadIdx.x;
    int v = (t < SCAN_B) ? g_bsum[t] : 0;
    int val = v;
    sh[t] = val;
    __syncthreads();
#pragma unroll
    for (int off = 1; off < 128; off <<= 1) {
        int tmp = (t >= off) ? sh[t - off] : 0;
        __syncthreads();
        val += tmp;
        sh[t] = val;
        __syncthreads();
    }
    if (t < SCAN_B) g_boff[t] = val - v;
}

__global__ void k_scan_add() {
    int i = blockIdx.x * blockDim.x + threadIdx.x;
    if (i < NU) {
        int r = g_rowptr[i] + g_boff[i >> 10];
        g_rowptr[i] = r;
        g_cursor[i] = r;
    }
    if (i == 0) g_rowptr[NU] = NE;
}

__global__ void k_scatter(const int* __restrict__ src, const int* __restrict__ dst) {
    int i = blockIdx.x * blockDim.x + threadIdx.x;
    if (i < NE / 8) {
        int4 d0 = ((const int4*)dst)[2 * i];
        int4 d1 = ((const int4*)dst)[2 * i + 1];
        int4 s0 = ((const int4*)src)[2 * i];
        int4 s1 = ((const int4*)src)[2 * i + 1];
        int p0 = atomicAdd(&g_cursor[d0.x], 1);
        int p1 = atomicAdd(&g_cursor[d0.y], 1);
        int p2 = atomicAdd(&g_cursor[d0.z], 1);
        int p3 = atomicAdd(&g_cursor[d0.w], 1);
        int p4 = atomicAdd(&g_cursor[d1.x], 1);
        int p5 = atomicAdd(&g_cursor[d1.y], 1);
        int p6 = atomicAdd(&g_cursor[d1.z], 1);
        int p7 = atomicAdd(&g_cursor[d1.w], 1);
        g_esrc[p0] = s0.x; g_esrc[p1] = s0.y; g_esrc[p2] = s0.z; g_esrc[p3] = s0.w;
        g_esrc[p4] = s1.x; g_esrc[p5] = s1.y; g_esrc[p6] = s1.z; g_esrc[p7] = s1.w;
    }
}

// ---------------- high-occupancy neighbor-mean aggregation ----------------
__device__ __forceinline__ void agg_row(
    const float* __restrict__ table, int row, int lane, float* __restrict__ dstv)
{
    int beg = g_rowptr[row], end = g_rowptr[row + 1];
    int deg = end - beg;
    float4 a = make_float4(0.f, 0.f, 0.f, 0.f);
    for (int base = 0; base < deg; base += 32) {
        int rem = deg - base;
        int n = rem < 32 ? rem : 32;
        int myi = (lane < n) ? g_esrc[beg + base + lane] : 0;
        int j = 0;
        for (; j + 8 <= n; j += 8) {
            int s0 = __shfl_sync(0xffffffffu, myi, j + 0);
            int s1 = __shfl_sync(0xffffffffu, myi, j + 1);
            int s2 = __shfl_sync(0xffffffffu, myi, j + 2);
            int s3 = __shfl_sync(0xffffffffu, myi, j + 3);
            int s4 = __shfl_sync(0xffffffffu, myi, j + 4);
            int s5 = __shfl_sync(0xffffffffu, myi, j + 5);
            int s6 = __shfl_sync(0xffffffffu, myi, j + 6);
            int s7 = __shfl_sync(0xffffffffu, myi, j + 7);
            float4 x0 = ((const float4*)(table + (size_t)s0 * D))[lane];
            float4 x1 = ((const float4*)(table + (size_t)s1 * D))[lane];
            float4 x2 = ((const float4*)(table + (size_t)s2 * D))[lane];
            float4 x3 = ((const float4*)(table + (size_t)s3 * D))[lane];
            float4 x4 = ((const float4*)(table + (size_t)s4 * D))[lane];
            float4 x5 = ((const float4*)(table + (size_t)s5 * D))[lane];
            float4 x6 = ((const float4*)(table + (size_t)s6 * D))[lane];
            float4 x7 = ((const float4*)(table + (size_t)s7 * D))[lane];
            a.x += ((x0.x + x1.x) + (x2.x + x3.x)) + ((x4.x + x5.x) + (x6.x + x7.x));
            a.y += ((x0.y + x1.y) + (x2.y + x3.y)) + ((x4.y + x5.y) + (x6.y + x7.y));
            a.z += ((x0.z + x1.z) + (x2.z + x3.z)) + ((x4.z + x5.z) + (x6.z + x7.z));
            a.w += ((x0.w + x1.w) + (x2.w + x3.w)) + ((x4.w + x5.w) + (x6.w + x7.w));
        }
        for (; j < n; j++) {
            int s = __shfl_sync(0xffffffffu, myi, j);
            float4 x = ((const float4*)(table + (size_t)s * D))[lane];
            a.x += x.x; a.y += x.y; a.z += x.z; a.w += x.w;
        }
    }
    float inv = 1.f / fmaxf((float)deg, 1.f);
    a.x *= inv; a.y *= inv; a.z *= inv; a.w *= inv;
    ((float4*)dstv)[lane] = a;
}

__global__ __launch_bounds__(256) void k_agg1(const float* __restrict__ feat) {
    int row  = (blockIdx.x * blockDim.x + threadIdx.x) >> 5;
    int lane = threadIdx.x & 31;
    if (row < NU) agg_row(feat, row, lane, g_hn + (size_t)row * D);
}

__global__ __launch_bounds__(256) void k_agg2(const int* __restrict__ users) {
    int b    = (blockIdx.x * blockDim.x + threadIdx.x) >> 5;
    int lane = threadIdx.x & 31;
    if (b < NB) agg_row(g_h1, users[b], lane, g_hn2 + (size_t)b * D);
}

// ---------------- FFMA2 single-weight GEMM core ----------------
#define GM_SMEM ((16384 + 128 + 64 * D) * (int)sizeof(float))

__device__ __forceinline__ void gemm_one8(
    const float* sX, const float* sW, int lr0, int lane, u64* acc0, u64* acc1)
{
#pragma unroll
    for (int j = 0; j < 8; j++) { acc0[j] = 0ull; acc1[j] = 0ull; }
#pragma unroll 4
    for (int k = 0; k < D; k += 2) {
        ulonglong2 wa = *(const ulonglong2*)(sW + k * D + lane * 4);
        ulonglong2 wb = *(const ulonglong2*)(sW + (k + 1) * D + lane * 4);
#pragma unroll
        for (int j = 0; j < 8; j++) {
            float2 x2 = *(const float2*)(sX + (lr0 + j) * D + k);
            u64 xx0 = dup2(x2.x), xx1 = dup2(x2.y);
            ffma2(acc0[j], xx0, wa.x); ffma2(acc1[j], xx0, wa.y);
            ffma2(acc0[j], xx1, wb.x); ffma2(acc1[j], xx1, wb.y);
        }
    }
}

__device__ __forceinline__ void stage_w(const float* __restrict__ W, float* sW, int tid) {
    const float4* g = (const float4*)W;
    float4* s = (float4*)sW;
    for (int i = tid; i < 4096; i += 256) s[i] = g[i];
}

__device__ __forceinline__ float epi4(u64 a0, u64 a1, float4 pa, float4 b4, float4& v) {
    float2 p01 = unpk(a0), p23 = unpk(a1);
    float t0 = p01.x + pa.x + b4.x, t1 = p01.y + pa.y + b4.y;
    float t2 = p23.x + pa.z + b4.z, t3 = p23.y + pa.w + b4.w;
    t0 = t0 > 0.f ? t0 : 0.2f * t0;
    t1 = t1 > 0.f ? t1 : 0.2f * t1;
    t2 = t2 > 0.f ? t2 : 0.2f * t2;
    t3 = t3 > 0.f ? t3 : 0.2f * t3;
    v = make_float4(t0, t1, t2, t3);
    return t0 * t0 + t1 * t1 + t2 * t2 + t3 * t3;
}

// ---------------- dense1 pass A: g_acc = feat @ Ws ----------------
__global__ __launch_bounds__(256, 2) void k_d1a(
    const float* __restrict__ feat, const float* __restrict__ Ws)
{
    extern __shared__ float sm[];
    float* sW = sm;
    float* sX = sm + 16384 + 128;
    const int tid = threadIdx.x, warp = tid >> 5, lane = tid & 31;
    stage_w(Ws, sW, tid);
    const int lr0 = warp * 8;
    const int r0 = blockIdx.x * 64;
#pragma unroll
    for (int j = 0; j < 8; j++) {
        int row = r0 + lr0 + j;
        ((float4*)(sX + (lr0 + j) * D))[lane] = (row < NU)
            ? ((const float4*)(feat + (size_t)row * D))[lane]
            : make_float4(0.f, 0.f, 0.f, 0.f);
    }
    __syncthreads();
    u64 acc0[8], acc1[8];
    gemm_one8(sX, sW, lr0, lane, acc0, acc1);
#pragma unroll
    for (int j = 0; j < 8; j++) {
        int row = r0 + lr0 + j;
        if (row < NU) {
            float2 p01 = unpk(acc0[j]), p23 = unpk(acc1[j]);
            ((float4*)(g_acc + (size_t)row * D))[lane] =
                make_float4(p01.x, p01.y, p23.x, p23.y);
        }
    }
}

// ---------------- dense1 pass B ----------------
__global__ __launch_bounds__(256, 2) void k_d1b(
    const float* __restrict__ Wn, const float* __restrict__ bias)
{
    extern __shared__ float sm[];
    float* sW = sm;
    float* sB = sm + 16384;
    float* sX = sm + 16384 + 128;
    const int tid = threadIdx.x, warp = tid >> 5, lane = tid & 31;
    stage_w(Wn, sW, tid);
    if (tid < 32) ((float4*)sB)[tid] = ((const float4*)bias)[tid];
    const int lr0 = warp * 8;
    const int r0 = blockIdx.x * 64;
#pragma unroll
    for (int j = 0; j < 8; j++) {
        int row = r0 + lr0 + j;
        ((float4*)(sX + (lr0 + j) * D))[lane] = (row < NU)
            ? ((const float4*)(g_hn + (size_t)row * D))[lane]
            : make_float4(0.f, 0.f, 0.f, 0.f);
    }
    __syncthreads();
    u64 acc0[8], acc1[8];
    gemm_one8(sX, sW, lr0, lane, acc0, acc1);

    float4 b4 = ((const float4*)sB)[lane];
    float4 v[8]; float ss[8];
#pragma unroll
    for (int j = 0; j < 8; j++) {
        int row = r0 + lr0 + j;
        float4 pa = (row < NU) ? ((const float4*)(g_acc + (size_t)row * D))[lane]
                               : make_float4(0.f, 0.f, 0.f, 0.f);
        ss[j] = epi4(acc0[j], acc1[j], pa, b4, v[j]);
    }
#pragma unroll
    for (int off = 16; off; off >>= 1) {
#pragma unroll
        for (int j = 0; j < 8; j++) ss[j] += __shfl_xor_sync(0xffffffffu, ss[j], off);
    }
#pragma unroll
    for (int j = 0; j < 8; j++) {
        int row = r0 + lr0 + j;
        if (row < NU) {
            float sc = 1.f / fmaxf(sqrtf(ss[j]), 1e-12f);
            ((float4*)(g_h1 + (size_t)row * D))[lane] =
                make_float4(v[j].x * sc, v[j].y * sc, v[j].z * sc, v[j].w * sc);
        }
    }
}

// ---------------- dense2 pass A ----------------
__global__ __launch_bounds__(256, 2) void k_d2a(
    const float* __restrict__ ufeat, const int* __restrict__ users,
    const float* __restrict__ Ws, float* __restrict__ out)
{
    extern __shared__ float sm[];
    float* sW = sm;
    float* sX = sm + 16384 + 128;
    const int tid = threadIdx.x, warp = tid >> 5, lane = tid & 31;
    stage_w(Ws, sW, tid);
    const int lr0 = warp * 8;
    const int r0 = blockIdx.x * 64;
#pragma unroll
    for (int j = 0; j < 8; j++) {
        int b = r0 + lr0 + j;
        int u = users[b];
        float4 x4 = ((const float4*)(g_h1 + (size_t)u * D))[lane];
        ((float4*)(sX + (lr0 + j) * D))[lane] = x4;
        ((float4*)(out + (size_t)b * 384))[lane]       = ((const float4*)(ufeat + (size_t)u * D))[lane];
        ((float4*)(out + (size_t)b * 384 + 128))[lane] = x4;
    }
    __syncthreads();
    u64 acc0[8], acc1[8];
    gemm_one8(sX, sW, lr0, lane, acc0, acc1);
#pragma unroll
    for (int j = 0; j < 8; j++) {
        int b = r0 + lr0 + j;
        float2 p01 = unpk(acc0[j]), p23 = unpk(acc1[j]);
        ((float4*)(g_acc + (size_t)b * D))[lane] = make_float4(p01.x, p01.y, p23.x, p23.y);
    }
}

// ---------------- dense2 pass B ----------------
__global__ __launch_bounds__(256, 2) void k_d2b(
    const float* __restrict__ Wn, const float* __restrict__ bias, float* __restrict__ out)
{
    extern __shared__ float sm[];
    float* sW = sm;
    float* sB = sm + 16384;
    float* sX = sm + 16384 + 128;
    const int tid = threadIdx.x, warp = tid >> 5, lane = tid & 31;
    stage_w(Wn, sW, tid);
    if (tid < 32) ((float4*)sB)[tid] = ((const float4*)bias)[tid];
    const int lr0 = warp * 8;
    const int r0 = blockIdx.x * 64;
#pragma unroll
    for (int j = 0; j < 8; j++) {
        int b = r0 + lr0 + j;
        ((float4*)(sX + (lr0 + j) * D))[lane] =
            ((const float4*)(g_hn2 + (size_t)b * D))[lane];
    }
    __syncthreads();
    u64 acc0[8], acc1[8];
    gemm_one8(sX, sW, lr0, lane, acc0, acc1);

    float4 b4 = ((const float4*)sB)[lane];
    float4 v[8]; float ss[8];
#pragma unroll
    for (int j = 0; j < 8; j++) {
        int b = r0 + lr0 + j;
        float4 pa = ((const float4*)(g_acc + (size_t)b * D))[lane];
        ss[j] = epi4(acc0[j], acc1[j], pa, b4, v[j]);
    }
#pragma unroll
    for (int off = 16; off; off >>= 1) {
#pragma unroll
        for (int j = 0; j < 8; j++) ss[j] += __shfl_xor_sync(0xffffffffu, ss[j], off);
    }
#pragma unroll
    for (int j = 0; j < 8; j++) {
        float sc = 1.f / fmaxf(sqrtf(ss[j]), 1e-12f);
        int b = r0 + lr0 + j;
        ((float4*)(out + (size_t)b * 384 + 256))[lane] =
            make_float4(v[j].x * sc, v[j].y * sc, v[j].z * sc, v[j].w * sc);
    }
}

// ---------------- item tower pass 1 ----------------
__global__ __launch_bounds__(256, 2) void k_it1(
    const float* __restrict__ ifeat, const int* __restrict__ pos, const int* __restrict__ neg,
    const float* __restrict__ W0, const float* __restrict__ b0, float* __restrict__ out)
{
    extern __shared__ float sm[];
    float* sW = sm;
    float* sB = sm + 16384;
    float* sX = sm + 16384 + 128;
    const int tid = threadIdx.x, warp = tid >> 5, lane = tid & 31;
    stage_w(W0, sW, tid);
    if (tid < 32) ((float4*)sB)[tid] = ((const float4*)b0)[tid];
    const int lr0 = warp * 8;
    const int r0 = blockIdx.x * 64;
#pragma unroll
    for (int j = 0; j < 8; j++) {
        int rr = r0 + lr0 + j;
        int idx = (rr < NB) ? pos[rr] : neg[rr - NB];
        float4 x4 = ((const float4*)(ifeat + (size_t)idx * D))[lane];
        ((float4*)(sX + (lr0 + j) * D))[lane] = x4;
        ((float4*)(out + (size_t)(NB + rr) * 384))[lane] = x4;   // seg 0
    }
    __syncthreads();
    u64 acc0[8], acc1[8];
    gemm_one8(sX, sW, lr0, lane, acc0, acc1);

    float4 b4 = ((const float4*)sB)[lane];
    const float4 z4 = make_float4(0.f, 0.f, 0.f, 0.f);
    float4 v[8]; float ss[8];
#pragma unroll
    for (int j = 0; j < 8; j++) ss[j] = epi4(acc0[j], acc1[j], z4, b4, v[j]);
#pragma unroll
    for (int off = 16; off; off >>= 1) {
#pragma unroll
        for (int j = 0; j < 8; j++) ss[j] += __shfl_xor_sync(0xffffffffu, ss[j], off);
    }
#pragma unroll
    for (int j = 0; j < 8; j++) {
        float sc = 1.f / fmaxf(sqrtf(ss[j]), 1e-12f);
        int rr = r0 + lr0 + j;
        float4 o = make_float4(v[j].x * sc, v[j].y * sc, v[j].z * sc, v[j].w * sc);
        ((float4*)(g_hi + (size_t)rr * D))[lane] = o;
        ((float4*)(out + (size_t)(NB + rr) * 384 + 128))[lane] = o;  // seg 1
    }
}

// ---------------- item tower pass 2 ----------------
__global__ __launch_bounds__(256, 2) void k_it2(
    const float* __restrict__ W1, const float* __restrict__ b1, float* __restrict__ out)
{
    extern __shared__ float sm[];
    float* sW = sm;
    float* sB = sm + 16384;
    float* sX = sm + 16384 + 128;
    const int tid = threadIdx.x, warp = tid >> 5, lane = tid & 31;
    stage_w(W1, sW, tid);
    if (tid < 32) ((float4*)sB)[tid] = ((const float4*)b1)[tid];
    const int lr0 = warp * 8;
    const int r0 = blockIdx.x * 64;
#pragma unroll
    for (int j = 0; j < 8; j++) {
        int rr = r0 + lr0 + j;
        ((float4*)(sX + (lr0 + j) * D))[lane] =
            ((const float4*)(g_hi + (size_t)rr * D))[lane];
    }
    __syncthreads();
    u64 acc0[8], acc1[8];
    gemm_one8(sX, sW, lr0, lane, acc0, acc1);

    float4 b4 = ((const float4*)sB)[lane];
    const float4 z4 = make_float4(0.f, 0.f, 0.f, 0.f);
    float4 v[8]; float ss[8];
#pragma unroll
    for (int j = 0; j < 8; j++) ss[j] = epi4(acc0[j], acc1[j], z4, b4, v[j]);
#pragma unroll
    for (int off = 16; off; off >>= 1) {
#pragma unroll
        for (int j = 0; j < 8; j++) ss[j] += __shfl_xor_sync(0xffffffffu, ss[j], off);
    }
#pragma unroll
    for (int j = 0; j < 8; j++) {
        float sc = 1.f / fmaxf(sqrtf(ss[j]), 1e-12f);
        int rr = r0 + lr0 + j;
        ((float4*)(out + (size_t)(NB + rr) * 384 + 256))[lane] =
            make_float4(v[j].x * sc, v[j].y * sc, v[j].z * sc, v[j].w * sc);
    }
}

// ---------------- launch (stream fork/join for graph parallelism) ----------------
extern "C" void kernel_launch(void* const* d_in, const int* in_sizes, int n_in,
                              void* d_out, int out_size) {
    const int*   src   = (const int*)d_in[0];
    const int*   dst   = (const int*)d_in[1];
    const int*   users = (const int*)d_in[2];
    const int*   pos   = (const int*)d_in[3];
    const int*   neg   = (const int*)d_in[4];
    const float* ufeat = (const float*)d_in[5];
    const float* ifeat = (const float*)d_in[6];
    const float* Ws0   = (const float*)d_in[7];
    const float* Wn0   = (const float*)d_in[8];
    const float* bu0   = (const float*)d_in[9];
    const float* Wi0   = (const float*)d_in[10];
    const float* bi0   = (const float*)d_in[11];
    const float* Ws1   = (const float*)d_in[12];
    const float* Wn1   = (const float*)d_in[13];
    const float* bu1   = (const float*)d_in[14];
    const float* Wi1   = (const float*)d_in[15];
    const float* bi1   = (const float*)d_in[16];
    float* out = (float*)d_out;

    (void)cudaFuncSetAttribute(k_d1a, cudaFuncAttributeMaxDynamicSharedMemorySize, GM_SMEM);
    (void)cudaFuncSetAttribute(k_d1b, cudaFuncAttributeMaxDynamicSharedMemorySize, GM_SMEM);
    (void)cudaFuncSetAttribute(k_d2a, cudaFuncAttributeMaxDynamicSharedMemorySize, GM_SMEM);
    (void)cudaFuncSetAttribute(k_d2b, cudaFuncAttributeMaxDynamicSharedMemorySize, GM_SMEM);
    (void)cudaFuncSetAttribute(k_it1, cudaFuncAttributeMaxDynamicSharedMemorySize, GM_SMEM);
    (void)cudaFuncSetAttribute(k_it2, cudaFuncAttributeMaxDynamicSharedMemorySize, GM_SMEM);

    const int GD1 = (NU + 63) / 64;     // 1563
    const int GD2 = NB / 64;            // 256
    const int GIT = (2 * NB) / 64;      // 512

    // one-time stream/event setup (first call is the non-captured correctness run)
    static cudaStream_t sA = 0;
    static cudaEvent_t evFork = 0, evJoin = 0;
    static int inited = 0;
    if (!inited) {
        if (cudaStreamCreateWithFlags(&sA, cudaStreamNonBlocking) != cudaSuccess) sA = 0;
        if (cudaEventCreateWithFlags(&evFork, cudaEventDisableTiming) != cudaSuccess) evFork = 0;
        if (cudaEventCreateWithFlags(&evJoin, cudaEventDisableTiming) != cudaSuccess) evJoin = 0;
        inited = 1;
    }
    const bool par = (sA && evFork && evJoin);

    if (par) {
        // fork: chain A (item tower + d1a) on sA, chain B (CSR + agg1) on default
        cudaEventRecord(evFork, 0);
        cudaStreamWaitEvent(sA, evFork, 0);

        // chain B (default stream)
        k_zero      <<<(NU + 255) / 256, 256>>>();
        k_count     <<<(NE / 8 + 255) / 256, 256>>>(dst);
        // chain A (sA)
        k_it1       <<<GIT, 256, GM_SMEM, sA>>>(ifeat, pos, neg, Wi0, bi0, out);
        k_it2       <<<GIT, 256, GM_SMEM, sA>>>(Wi1, bi1, out);
        k_d1a       <<<GD1, 256, GM_SMEM, sA>>>(ufeat, Ws0);
        cudaEventRecord(evJoin, sA);
        // chain B continues
        k_scan_local<<<SCAN_B, 1024>>>();
        k_scan_top  <<<1, 128>>>();
        k_scan_add  <<<(NU + 255) / 256, 256>>>();
        k_scatter   <<<(NE / 8 + 255) / 256, 256>>>(src, dst);
        k_agg1      <<<(NU * 32 + 255) / 256, 256>>>(ufeat);

        // join: d1b needs g_acc (chain A) + g_hn (chain B)
        cudaStreamWaitEvent(0, evJoin, 0);
        k_d1b       <<<GD1, 256, GM_SMEM>>>(Wn0, bu0);
        k_agg2      <<<(NB * 32) / 256, 256>>>(users);
        k_d2a       <<<GD2, 256, GM_SMEM>>>(ufeat, users, Ws1, out);
        k_d2b       <<<GD2, 256, GM_SMEM>>>(Wn1, bu1, out);
    } else {
        // serial fallback (identical to R9)
        k_zero      <<<(NU + 255) / 256, 256>>>();
        k_count     <<<(NE / 8 + 255) / 256, 256>>>(dst);
        k_it1       <<<GIT, 256, GM_SMEM>>>(ifeat, pos, neg, Wi0, bi0, out);
        k_d1a       <<<GD1, 256, GM_SMEM>>>(ufeat, Ws0);
        k_scan_local<<<SCAN_B, 1024>>>();
        k_scan_top  <<<1, 128>>>();
        k_scan_add  <<<(NU + 255) / 256, 256>>>();
        k_scatter   <<<(NE / 8 + 255) / 256, 256>>>(src, dst);
        k_it2       <<<GIT, 256, GM_SMEM>>>(Wi1, bi1, out);
        k_agg1      <<<(NU * 32 + 255) / 256, 256>>>(ufeat);
        k_d1b       <<<GD1, 256, GM_SMEM>>>(Wn0, bu0);
        k_agg2      <<<(NB * 32) / 256, 256>>>(users);
        k_d2a       <<<GD2, 256, GM_SMEM>>>(ufeat, users, Ws1, out);
        k_d2b       <<<GD2, 256, GM_SMEM>>>(Wn1, bu1, out);
    }
}

// round 11
// speedup vs baseline: 1.4079x; 1.0243x over previous
#include <cuda_runtime.h>
#include <cstdint>

#define NU 100000
#define NE 1600000
#define NB 16384
#define D  128
#define SCAN_B 98   // ceil(NU / 1024)

typedef unsigned long long u64;

// ---- static scratch (no allocations allowed) ----
static __device__ int   g_rowptr[NU + 1];
static __device__ int   g_cursor[NU];
static __device__ int   g_esrc[NE];
static __device__ int   g_bsum[SCAN_B];
static __device__ int   g_boff[SCAN_B];
static __device__ float g_h1 [(size_t)NU * D];   // layer-1 user output
static __device__ float g_hn [(size_t)NU * D];   // layer-1 neighbor mean
static __device__ float g_hn2[(size_t)NB * D];   // layer-2 neighbor mean
static __device__ float g_acc[(size_t)NU * D];   // partial-GEMM accumulator
static __device__ float g_hi [(size_t)(2 * NB) * D];  // item layer-1 output

// ---------------- packed f32x2 helpers ----------------
__device__ __forceinline__ u64 dup2(float x) {
    u64 r; asm("mov.b64 %0, {%1, %1};" : "=l"(r) : "f"(x)); return r;
}
__device__ __forceinline__ void ffma2(u64& d, u64 a, u64 b) {
    asm("fma.rn.f32x2 %0, %1, %2, %0;" : "+l"(d) : "l"(a), "l"(b));
}
__device__ __forceinline__ float2 unpk(u64 v) {
    float2 r; asm("mov.b64 {%0, %1}, %2;" : "=f"(r.x), "=f"(r.y) : "l"(v)); return r;
}

// ---------------- CSR build ----------------
__global__ void k_zero() {
    int i = blockIdx.x * blockDim.x + threadIdx.x;
    if (i < NU) g_cursor[i] = 0;
}

__global__ void k_count(const int* __restrict__ dst) {
    int i = blockIdx.x * blockDim.x + threadIdx.x;
    if (i < NE / 8) {
        int4 d0 = ((const int4*)dst)[2 * i];
        int4 d1 = ((const int4*)dst)[2 * i + 1];
        atomicAdd(&g_cursor[d0.x], 1); atomicAdd(&g_cursor[d0.y], 1);
        atomicAdd(&g_cursor[d0.z], 1); atomicAdd(&g_cursor[d0.w], 1);
        atomicAdd(&g_cursor[d1.x], 1); atomicAdd(&g_cursor[d1.y], 1);
        atomicAdd(&g_cursor[d1.z], 1); atomicAdd(&g_cursor[d1.w], 1);
    }
}

__global__ __launch_bounds__(1024) void k_scan_local() {
    __shared__ int sh[1024];
    const int t = threadIdx.x;
    const int i = blockIdx.x * 1024 + t;
    int c = (i < NU) ? g_cursor[i] : 0;
    int val = c;
    sh[t] = val;
    __syncthreads();
#pragma unroll
    for (int off = 1; off < 1024; off <<= 1) {
        int tmp = (t >= off) ? sh[t - off] : 0;
        __syncthreads();
        val += tmp;
        sh[t] = val;
        __syncthreads();
    }
    if (i < NU) g_rowptr[i] = val - c;
    if (t == 1023) g_bsum[blockIdx.x] = val;
}

__global__ __launch_bounds__(128) void k_scan_top() {
    __shared__ int sh[128];
    const int t = threadIdx.x;
    int v = (t < SCAN_B) ? g_bsum[t] : 0;
    int val = v;
    sh[t] = val;
    __syncthreads();
#pragma unroll
    for (int off = 1; off < 128; off <<= 1) {
        int tmp = (t >= off) ? sh[t - off] : 0;
        __syncthreads();
        val += tmp;
        sh[t] = val;
        __syncthreads();
    }
    if (t < SCAN_B) g_boff[t] = val - v;
}

__global__ void k_scan_add() {
    int i = blockIdx.x * blockDim.x + threadIdx.x;
    if (i < NU) {
        int r = g_rowptr[i] + g_boff[i >> 10];
        g_rowptr[i] = r;
        g_cursor[i] = r;
    }
    if (i == 0) g_rowptr[NU] = NE;
}

__global__ void k_scatter(const int* __restrict__ src, const int* __restrict__ dst) {
    int i = blockIdx.x * blockDim.x + threadIdx.x;
    if (i < NE / 8) {
        int4 d0 = ((const int4*)dst)[2 * i];
        int4 d1 = ((const int4*)dst)[2 * i + 1];
        int4 s0 = ((const int4*)src)[2 * i];
        int4 s1 = ((const int4*)src)[2 * i + 1];
        int p0 = atomicAdd(&g_cursor[d0.x], 1);
        int p1 = atomicAdd(&g_cursor[d0.y], 1);
        int p2 = atomicAdd(&g_cursor[d0.z], 1);
        int p3 = atomicAdd(&g_cursor[d0.w], 1);
        int p4 = atomicAdd(&g_cursor[d1.x], 1);
        int p5 = atomicAdd(&g_cursor[d1.y], 1);
        int p6 = atomicAdd(&g_cursor[d1.z], 1);
        int p7 = atomicAdd(&g_cursor[d1.w], 1);
        g_esrc[p0] = s0.x; g_esrc[p1] = s0.y; g_esrc[p2] = s0.z; g_esrc[p3] = s0.w;
        g_esrc[p4] = s1.x; g_esrc[p5] = s1.y; g_esrc[p6] = s1.z; g_esrc[p7] = s1.w;
    }
}

// ---------------- high-occupancy neighbor-mean aggregation ----------------
__device__ __forceinline__ void agg_row(
    const float* __restrict__ table, int row, int lane, float* __restrict__ dstv)
{
    int beg = g_rowptr[row], end = g_rowptr[row + 1];
    int deg = end - beg;
    float4 a = make_float4(0.f, 0.f, 0.f, 0.f);
    for (int base = 0; base < deg; base += 32) {
        int rem = deg - base;
        int n = rem < 32 ? rem : 32;
        int myi = (lane < n) ? g_esrc[beg + base + lane] : 0;
        int j = 0;
        for (; j + 8 <= n; j += 8) {
            int s0 = __shfl_sync(0xffffffffu, myi, j + 0);
            int s1 = __shfl_sync(0xffffffffu, myi, j + 1);
            int s2 = __shfl_sync(0xffffffffu, myi, j + 2);
            int s3 = __shfl_sync(0xffffffffu, myi, j + 3);
            int s4 = __shfl_sync(0xffffffffu, myi, j + 4);
            int s5 = __shfl_sync(0xffffffffu, myi, j + 5);
            int s6 = __shfl_sync(0xffffffffu, myi, j + 6);
            int s7 = __shfl_sync(0xffffffffu, myi, j + 7);
            float4 x0 = ((const float4*)(table + (size_t)s0 * D))[lane];
            float4 x1 = ((const float4*)(table + (size_t)s1 * D))[lane];
            float4 x2 = ((const float4*)(table + (size_t)s2 * D))[lane];
            float4 x3 = ((const float4*)(table + (size_t)s3 * D))[lane];
            float4 x4 = ((const float4*)(table + (size_t)s4 * D))[lane];
            float4 x5 = ((const float4*)(table + (size_t)s5 * D))[lane];
            float4 x6 = ((const float4*)(table + (size_t)s6 * D))[lane];
            float4 x7 = ((const float4*)(table + (size_t)s7 * D))[lane];
            a.x += ((x0.x + x1.x) + (x2.x + x3.x)) + ((x4.x + x5.x) + (x6.x + x7.x));
            a.y += ((x0.y + x1.y) + (x2.y + x3.y)) + ((x4.y + x5.y) + (x6.y + x7.y));
            a.z += ((x0.z + x1.z) + (x2.z + x3.z)) + ((x4.z + x5.z) + (x6.z + x7.z));
            a.w += ((x0.w + x1.w) + (x2.w + x3.w)) + ((x4.w + x5.w) + (x6.w + x7.w));
        }
        for (; j < n; j++) {
            int s = __shfl_sync(0xffffffffu, myi, j);
            float4 x = ((const float4*)(table + (size_t)s * D))[lane];
            a.x += x.x; a.y += x.y; a.z += x.z; a.w += x.w;
        }
    }
    float inv = 1.f / fmaxf((float)deg, 1.f);
    a.x *= inv; a.y *= inv; a.z *= inv; a.w *= inv;
    ((float4*)dstv)[lane] = a;
}

__global__ __launch_bounds__(256) void k_agg1(const float* __restrict__ feat) {
    int row  = (blockIdx.x * blockDim.x + threadIdx.x) >> 5;
    int lane = threadIdx.x & 31;
    if (row < NU) agg_row(feat, row, lane, g_hn + (size_t)row * D);
}

__global__ __launch_bounds__(256) void k_agg2(const int* __restrict__ users) {
    int b    = (blockIdx.x * blockDim.x + threadIdx.x) >> 5;
    int lane = threadIdx.x & 31;
    if (b < NB) agg_row(g_h1, users[b], lane, g_hn2 + (size_t)b * D);
}

// ---------------- FFMA2 single-weight GEMM core ----------------
#define GM_SMEM ((16384 + 128 + 64 * D) * (int)sizeof(float))

__device__ __forceinline__ void gemm_one8(
    const float* sX, const float* sW, int lr0, int lane, u64* acc0, u64* acc1)
{
#pragma unroll
    for (int j = 0; j < 8; j++) { acc0[j] = 0ull; acc1[j] = 0ull; }
#pragma unroll 4
    for (int k = 0; k < D; k += 2) {
        ulonglong2 wa = *(const ulonglong2*)(sW + k * D + lane * 4);
        ulonglong2 wb = *(const ulonglong2*)(sW + (k + 1) * D + lane * 4);
#pragma unroll
        for (int j = 0; j < 8; j++) {
            float2 x2 = *(const float2*)(sX + (lr0 + j) * D + k);
            u64 xx0 = dup2(x2.x), xx1 = dup2(x2.y);
            ffma2(acc0[j], xx0, wa.x); ffma2(acc1[j], xx0, wa.y);
            ffma2(acc0[j], xx1, wb.x); ffma2(acc1[j], xx1, wb.y);
        }
    }
}

__device__ __forceinline__ void stage_w(const float* __restrict__ W, float* sW, int tid) {
    const float4* g = (const float4*)W;
    float4* s = (float4*)sW;
    for (int i = tid; i < 4096; i += 256) s[i] = g[i];
}

__device__ __forceinline__ float epi4(u64 a0, u64 a1, float4 pa, float4 b4, float4& v) {
    float2 p01 = unpk(a0), p23 = unpk(a1);
    float t0 = p01.x + pa.x + b4.x, t1 = p01.y + pa.y + b4.y;
    float t2 = p23.x + pa.z + b4.z, t3 = p23.y + pa.w + b4.w;
    t0 = t0 > 0.f ? t0 : 0.2f * t0;
    t1 = t1 > 0.f ? t1 : 0.2f * t1;
    t2 = t2 > 0.f ? t2 : 0.2f * t2;
    t3 = t3 > 0.f ? t3 : 0.2f * t3;
    v = make_float4(t0, t1, t2, t3);
    return t0 * t0 + t1 * t1 + t2 * t2 + t3 * t3;
}

// ---------------- dense1 pass A: g_acc = feat @ Ws ----------------
__global__ __launch_bounds__(256, 2) void k_d1a(
    const float* __restrict__ feat, const float* __restrict__ Ws)
{
    extern __shared__ float sm[];
    float* sW = sm;
    float* sX = sm + 16384 + 128;
    const int tid = threadIdx.x, warp = tid >> 5, lane = tid & 31;
    stage_w(Ws, sW, tid);
    const int lr0 = warp * 8;
    const int r0 = blockIdx.x * 64;
#pragma unroll
    for (int j = 0; j < 8; j++) {
        int row = r0 + lr0 + j;
        ((float4*)(sX + (lr0 + j) * D))[lane] = (row < NU)
            ? ((const float4*)(feat + (size_t)row * D))[lane]
            : make_float4(0.f, 0.f, 0.f, 0.f);
    }
    __syncthreads();
    u64 acc0[8], acc1[8];
    gemm_one8(sX, sW, lr0, lane, acc0, acc1);
#pragma unroll
    for (int j = 0; j < 8; j++) {
        int row = r0 + lr0 + j;
        if (row < NU) {
            float2 p01 = unpk(acc0[j]), p23 = unpk(acc1[j]);
            ((float4*)(g_acc + (size_t)row * D))[lane] =
                make_float4(p01.x, p01.y, p23.x, p23.y);
        }
    }
}

// ---------------- dense1 pass B ----------------
__global__ __launch_bounds__(256, 2) void k_d1b(
    const float* __restrict__ Wn, const float* __restrict__ bias)
{
    extern __shared__ float sm[];
    float* sW = sm;
    float* sB = sm + 16384;
    float* sX = sm + 16384 + 128;
    const int tid = threadIdx.x, warp = tid >> 5, lane = tid & 31;
    stage_w(Wn, sW, tid);
    if (tid < 32) ((float4*)sB)[tid] = ((const float4*)bias)[tid];
    const int lr0 = warp * 8;
    const int r0 = blockIdx.x * 64;
#pragma unroll
    for (int j = 0; j < 8; j++) {
        int row = r0 + lr0 + j;
        ((float4*)(sX + (lr0 + j) * D))[lane] = (row < NU)
            ? ((const float4*)(g_hn + (size_t)row * D))[lane]
            : make_float4(0.f, 0.f, 0.f, 0.f);
    }
    __syncthreads();
    u64 acc0[8], acc1[8];
    gemm_one8(sX, sW, lr0, lane, acc0, acc1);

    float4 b4 = ((const float4*)sB)[lane];
    float4 v[8]; float ss[8];
#pragma unroll
    for (int j = 0; j < 8; j++) {
        int row = r0 + lr0 + j;
        float4 pa = (row < NU) ? ((const float4*)(g_acc + (size_t)row * D))[lane]
                               : make_float4(0.f, 0.f, 0.f, 0.f);
        ss[j] = epi4(acc0[j], acc1[j], pa, b4, v[j]);
    }
#pragma unroll
    for (int off = 16; off; off >>= 1) {
#pragma unroll
        for (int j = 0; j < 8; j++) ss[j] += __shfl_xor_sync(0xffffffffu, ss[j], off);
    }
#pragma unroll
    for (int j = 0; j < 8; j++) {
        int row = r0 + lr0 + j;
        if (row < NU) {
            float sc = 1.f / fmaxf(sqrtf(ss[j]), 1e-12f);
            ((float4*)(g_h1 + (size_t)row * D))[lane] =
                make_float4(v[j].x * sc, v[j].y * sc, v[j].z * sc, v[j].w * sc);
        }
    }
}

// ---------------- dense2 pass A ----------------
__global__ __launch_bounds__(256, 2) void k_d2a(
    const float* __restrict__ ufeat, const int* __restrict__ users,
    const float* __restrict__ Ws, float* __restrict__ out)
{
    extern __shared__ float sm[];
    float* sW = sm;
    float* sX = sm + 16384 + 128;
    const int tid = threadIdx.x, warp = tid >> 5, lane = tid & 31;
    stage_w(Ws, sW, tid);
    const int lr0 = warp * 8;
    const int r0 = blockIdx.x * 64;
#pragma unroll
    for (int j = 0; j < 8; j++) {
        int b = r0 + lr0 + j;
        int u = users[b];
        float4 x4 = ((const float4*)(g_h1 + (size_t)u * D))[lane];
        ((float4*)(sX + (lr0 + j) * D))[lane] = x4;
        ((float4*)(out + (size_t)b * 384))[lane]       = ((const float4*)(ufeat + (size_t)u * D))[lane];
        ((float4*)(out + (size_t)b * 384 + 128))[lane] = x4;
    }
    __syncthreads();
    u64 acc0[8], acc1[8];
    gemm_one8(sX, sW, lr0, lane, acc0, acc1);
#pragma unroll
    for (int j = 0; j < 8; j++) {
        int b = r0 + lr0 + j;
        float2 p01 = unpk(acc0[j]), p23 = unpk(acc1[j]);
        ((float4*)(g_acc + (size_t)b * D))[lane] = make_float4(p01.x, p01.y, p23.x, p23.y);
    }
}

// ---------------- dense2 pass B ----------------
__global__ __launch_bounds__(256, 2) void k_d2b(
    const float* __restrict__ Wn, const float* __restrict__ bias, float* __restrict__ out)
{
    extern __shared__ float sm[];
    float* sW = sm;
    float* sB = sm + 16384;
    float* sX = sm + 16384 + 128;
    const int tid = threadIdx.x, warp = tid >> 5, lane = tid & 31;
    stage_w(Wn, sW, tid);
    if (tid < 32) ((float4*)sB)[tid] = ((const float4*)bias)[tid];
    const int lr0 = warp * 8;
    const int r0 = blockIdx.x * 64;
#pragma unroll
    for (int j = 0; j < 8; j++) {
        int b = r0 + lr0 + j;
        ((float4*)(sX + (lr0 + j) * D))[lane] =
            ((const float4*)(g_hn2 + (size_t)b * D))[lane];
    }
    __syncthreads();
    u64 acc0[8], acc1[8];
    gemm_one8(sX, sW, lr0, lane, acc0, acc1);

    float4 b4 = ((const float4*)sB)[lane];
    float4 v[8]; float ss[8];
#pragma unroll
    for (int j = 0; j < 8; j++) {
        int b = r0 + lr0 + j;
        float4 pa = ((const float4*)(g_acc + (size_t)b * D))[lane];
        ss[j] = epi4(acc0[j], acc1[j], pa, b4, v[j]);
    }
#pragma unroll
    for (int off = 16; off; off >>= 1) {
#pragma unroll
        for (int j = 0; j < 8; j++) ss[j] += __shfl_xor_sync(0xffffffffu, ss[j], off);
    }
#pragma unroll
    for (int j = 0; j < 8; j++) {
        float sc = 1.f / fmaxf(sqrtf(ss[j]), 1e-12f);
        int b = r0 + lr0 + j;
        ((float4*)(out + (size_t)b * 384 + 256))[lane] =
            make_float4(v[j].x * sc, v[j].y * sc, v[j].z * sc, v[j].w * sc);
    }
}

// ---------------- item tower pass 1 ----------------
__global__ __launch_bounds__(256, 2) void k_it1(
    const float* __restrict__ ifeat, const int* __restrict__ pos, const int* __restrict__ neg,
    const float* __restrict__ W0, const float* __restrict__ b0, float* __restrict__ out)
{
    extern __shared__ float sm[];
    float* sW = sm;
    float* sB = sm + 16384;
    float* sX = sm + 16384 + 128;
    const int tid = threadIdx.x, warp = tid >> 5, lane = tid & 31;
    stage_w(W0, sW, tid);
    if (tid < 32) ((float4*)sB)[tid] = ((const float4*)b0)[tid];
    const int lr0 = warp * 8;
    const int r0 = blockIdx.x * 64;
#pragma unroll
    for (int j = 0; j < 8; j++) {
        int rr = r0 + lr0 + j;
        int idx = (rr < NB) ? pos[rr] : neg[rr - NB];
        float4 x4 = ((const float4*)(ifeat + (size_t)idx * D))[lane];
        ((float4*)(sX + (lr0 + j) * D))[lane] = x4;
        ((float4*)(out + (size_t)(NB + rr) * 384))[lane] = x4;   // seg 0
    }
    __syncthreads();
    u64 acc0[8], acc1[8];
    gemm_one8(sX, sW, lr0, lane, acc0, acc1);

    float4 b4 = ((const float4*)sB)[lane];
    const float4 z4 = make_float4(0.f, 0.f, 0.f, 0.f);
    float4 v[8]; float ss[8];
#pragma unroll
    for (int j = 0; j < 8; j++) ss[j] = epi4(acc0[j], acc1[j], z4, b4, v[j]);
#pragma unroll
    for (int off = 16; off; off >>= 1) {
#pragma unroll
        for (int j = 0; j < 8; j++) ss[j] += __shfl_xor_sync(0xffffffffu, ss[j], off);
    }
#pragma unroll
    for (int j = 0; j < 8; j++) {
        float sc = 1.f / fmaxf(sqrtf(ss[j]), 1e-12f);
        int rr = r0 + lr0 + j;
        float4 o = make_float4(v[j].x * sc, v[j].y * sc, v[j].z * sc, v[j].w * sc);
        ((float4*)(g_hi + (size_t)rr * D))[lane] = o;
        ((float4*)(out + (size_t)(NB + rr) * 384 + 128))[lane] = o;  // seg 1
    }
}

// ---------------- item tower pass 2 ----------------
__global__ __launch_bounds__(256, 2) void k_it2(
    const float* __restrict__ W1, const float* __restrict__ b1, float* __restrict__ out)
{
    extern __shared__ float sm[];
    float* sW = sm;
    float* sB = sm + 16384;
    float* sX = sm + 16384 + 128;
    const int tid = threadIdx.x, warp = tid >> 5, lane = tid & 31;
    stage_w(W1, sW, tid);
    if (tid < 32) ((float4*)sB)[tid] = ((const float4*)b1)[tid];
    const int lr0 = warp * 8;
    const int r0 = blockIdx.x * 64;
#pragma unroll
    for (int j = 0; j < 8; j++) {
        int rr = r0 + lr0 + j;
        ((float4*)(sX + (lr0 + j) * D))[lane] =
            ((const float4*)(g_hi + (size_t)rr * D))[lane];
    }
    __syncthreads();
    u64 acc0[8], acc1[8];
    gemm_one8(sX, sW, lr0, lane, acc0, acc1);

    float4 b4 = ((const float4*)sB)[lane];
    const float4 z4 = make_float4(0.f, 0.f, 0.f, 0.f);
    float4 v[8]; float ss[8];
#pragma unroll
    for (int j = 0; j < 8; j++) ss[j] = epi4(acc0[j], acc1[j], z4, b4, v[j]);
#pragma unroll
    for (int off = 16; off; off >>= 1) {
#pragma unroll
        for (int j = 0; j < 8; j++) ss[j] += __shfl_xor_sync(0xffffffffu, ss[j], off);
    }
#pragma unroll
    for (int j = 0; j < 8; j++) {
        float sc = 1.f / fmaxf(sqrtf(ss[j]), 1e-12f);
        int rr = r0 + lr0 + j;
        ((float4*)(out + (size_t)(NB + rr) * 384 + 256))[lane] =
            make_float4(v[j].x * sc, v[j].y * sc, v[j].z * sc, v[j].w * sc);
    }
}

// ---------------- launch (refined fork/join schedule) ----------------
extern "C" void kernel_launch(void* const* d_in, const int* in_sizes, int n_in,
                              void* d_out, int out_size) {
    const int*   src   = (const int*)d_in[0];
    const int*   dst   = (const int*)d_in[1];
    const int*   users = (const int*)d_in[2];
    const int*   pos   = (const int*)d_in[3];
    const int*   neg   = (const int*)d_in[4];
    const float* ufeat = (const float*)d_in[5];
    const float* ifeat = (const float*)d_in[6];
    const float* Ws0   = (const float*)d_in[7];
    const float* Wn0   = (const float*)d_in[8];
    const float* bu0   = (const float*)d_in[9];
    const float* Wi0   = (const float*)d_in[10];
    const float* bi0   = (const float*)d_in[11];
    const float* Ws1   = (const float*)d_in[12];
    const float* Wn1   = (const float*)d_in[13];
    const float* bu1   = (const float*)d_in[14];
    const float* Wi1   = (const float*)d_in[15];
    const float* bi1   = (const float*)d_in[16];
    float* out = (float*)d_out;

    (void)cudaFuncSetAttribute(k_d1a, cudaFuncAttributeMaxDynamicSharedMemorySize, GM_SMEM);
    (void)cudaFuncSetAttribute(k_d1b, cudaFuncAttributeMaxDynamicSharedMemorySize, GM_SMEM);
    (void)cudaFuncSetAttribute(k_d2a, cudaFuncAttributeMaxDynamicSharedMemorySize, GM_SMEM);
    (void)cudaFuncSetAttribute(k_d2b, cudaFuncAttributeMaxDynamicSharedMemorySize, GM_SMEM);
    (void)cudaFuncSetAttribute(k_it1, cudaFuncAttributeMaxDynamicSharedMemorySize, GM_SMEM);
    (void)cudaFuncSetAttribute(k_it2, cudaFuncAttributeMaxDynamicSharedMemorySize, GM_SMEM);

    const int GD1 = (NU + 63) / 64;     // 1563
    const int GD2 = NB / 64;            // 256
    const int GIT = (2 * NB) / 64;      // 512

    // one-time stream/event setup (first call is the non-captured correctness run)
    static cudaStream_t sA = 0;
    static cudaEvent_t evFork = 0, evAgg1 = 0, evIt1 = 0, evD1b = 0, evD2a = 0;
    static int inited = 0;
    if (!inited) {
        if (cudaStreamCreateWithFlags(&sA, cudaStreamNonBlocking) != cudaSuccess) sA = 0;
        if (cudaEventCreateWithFlags(&evFork, cudaEventDisableTiming) != cudaSuccess) evFork = 0;
        if (cudaEventCreateWithFlags(&evAgg1, cudaEventDisableTiming) != cudaSuccess) evAgg1 = 0;
        if (cudaEventCreateWithFlags(&evIt1,  cudaEventDisableTiming) != cudaSuccess) evIt1 = 0;
        if (cudaEventCreateWithFlags(&evD1b,  cudaEventDisableTiming) != cudaSuccess) evD1b = 0;
        if (cudaEventCreateWithFlags(&evD2a,  cudaEventDisableTiming) != cudaSuccess) evD2a = 0;
        inited = 1;
    }
    const bool par = (sA && evFork && evAgg1 && evIt1 && evD1b && evD2a);

    if (par) {
        cudaEventRecord(evFork, 0);
        cudaStreamWaitEvent(sA, evFork, 0);

        // chain A (sA): it1 -> d1a -> [agg1] -> d1b -> d2a
        k_it1       <<<GIT, 256, GM_SMEM, sA>>>(ifeat, pos, neg, Wi0, bi0, out);
        cudaEventRecord(evIt1, sA);
        k_d1a       <<<GD1, 256, GM_SMEM, sA>>>(ufeat, Ws0);

        // chain B (default): CSR -> agg1
        k_zero      <<<(NU + 255) / 256, 256>>>();
        k_count     <<<(NE / 8 + 255) / 256, 256>>>(dst);
        k_scan_local<<<SCAN_B, 1024>>>();
        k_scan_top  <<<1, 128>>>();
        k_scan_add  <<<(NU + 255) / 256, 256>>>();
        k_scatter   <<<(NE / 8 + 255) / 256, 256>>>(src, dst);
        k_agg1      <<<(NU * 32 + 255) / 256, 256>>>(ufeat);
        cudaEventRecord(evAgg1, 0);

        // it2 fills idle time on default stream (needs only it1)
        cudaStreamWaitEvent(0, evIt1, 0);
        k_it2       <<<GIT, 256, GM_SMEM>>>(Wi1, bi1, out);

        // chain A continues: d1b needs g_acc (d1a, same stream) + g_hn (agg1)
        cudaStreamWaitEvent(sA, evAgg1, 0);
        k_d1b       <<<GD1, 256, GM_SMEM, sA>>>(Wn0, bu0);
        cudaEventRecord(evD1b, sA);
        k_d2a       <<<GD2, 256, GM_SMEM, sA>>>(ufeat, users, Ws1, out);
        cudaEventRecord(evD2a, sA);

        // default: agg2 (needs g_h1) runs concurrently with d2a
        cudaStreamWaitEvent(0, evD1b, 0);
        k_agg2      <<<(NB * 32) / 256, 256>>>(users);

        // join: d2b needs g_acc (d2a) + g_hn2 (agg2)
        cudaStreamWaitEvent(0, evD2a, 0);
        k_d2b       <<<GD2, 256, GM_SMEM>>>(Wn1, bu1, out);
    } else {
        // serial fallback
        k_zero      <<<(NU + 255) / 256, 256>>>();
        k_count     <<<(NE / 8 + 255) / 256, 256>>>(dst);
        k_it1       <<<GIT, 256, GM_SMEM>>>(ifeat, pos, neg, Wi0, bi0, out);
        k_d1a       <<<GD1, 256, GM_SMEM>>>(ufeat, Ws0);
        k_scan_local<<<SCAN_B, 1024>>>();
        k_scan_top  <<<1, 128>>>();
        k_scan_add  <<<(NU + 255) / 256, 256>>>();
        k_scatter   <<<(NE / 8 + 255) / 256, 256>>>(src, dst);
        k_it2       <<<GIT, 256, GM_SMEM>>>(Wi1, bi1, out);
        k_agg1      <<<(NU * 32 + 255) / 256, 256>>>(ufeat);
        k_d1b       <<<GD1, 256, GM_SMEM>>>(Wn0, bu0);
        k_agg2      <<<(NB * 32) / 256, 256>>>(users);
        k_d2a       <<<GD2, 256, GM_SMEM>>>(ufeat, users, Ws1, out);
        k_d2b       <<<GD2, 256, GM_SMEM>>>(Wn1, bu1, out);
    }
}